// round 4
// baseline (speedup 1.0000x reference)
#include <cuda_runtime.h>

#define DM   1024
#define NH   16
#define HD   64
#define BSZ  4
#define TSEQ 2048
#define MROWS (BSZ * TSEQ)   // 8192

// Scratch (allocation-free rule: __device__ globals)
__device__ float g_Q[(size_t)BSZ * NH * TSEQ * HD];   // [B,H,T,hd]
__device__ float g_K[(size_t)BSZ * NH * TSEQ * HD];
__device__ float g_V[(size_t)BSZ * NH * TSEQ * HD];
__device__ float g_ctx[(size_t)MROWS * DM];           // [B,T,D]

// ---------------------------------------------------------------------------
// SGEMM: C[M=8192, N=1024] = A[8192,1024] @ W[1024,1024] + bias
// SCATTER=1: write into [B,H,T,hd] head layout. SCATTER=0: row-major [M,N].
// 128x128 block tile, K-tile 16, 256 threads, 8x8 register microtile.
// ---------------------------------------------------------------------------
template <int SCATTER>
__global__ void __launch_bounds__(256, 2)
gemm_bias(const float* __restrict__ A, const float* __restrict__ W,
          const float* __restrict__ bias, float* __restrict__ out)
{
    __shared__ float As[16][132];   // transposed A tile: As[k][m], pad for conflicts
    __shared__ float Bs[16][128];   // Bs[k][n]

    const int tid = threadIdx.x;
    const int tx = tid & 15;        // 16 column groups
    const int ty = tid >> 4;        // 16 row groups
    const int m0 = blockIdx.y * 128;
    const int n0 = blockIdx.x * 128;

    float acc[8][8];
#pragma unroll
    for (int i = 0; i < 8; i++)
#pragma unroll
        for (int j = 0; j < 8; j++) acc[i][j] = 0.f;

    for (int k0 = 0; k0 < DM; k0 += 16) {
        // Load A tile (128 rows x 16 cols) as float4, store transposed
#pragma unroll
        for (int i = 0; i < 2; i++) {
            int lin = tid + i * 256;          // 0..511
            int row = lin >> 2;               // 0..127
            int c4  = lin & 3;                // 0..3
            float4 v = *reinterpret_cast<const float4*>(
                &A[(size_t)(m0 + row) * DM + k0 + c4 * 4]);
            As[c4 * 4 + 0][row] = v.x;
            As[c4 * 4 + 1][row] = v.y;
            As[c4 * 4 + 2][row] = v.z;
            As[c4 * 4 + 3][row] = v.w;
        }
        // Load W tile (16 rows x 128 cols) as float4
#pragma unroll
        for (int i = 0; i < 2; i++) {
            int lin = tid + i * 256;          // 0..511
            int row = lin >> 5;               // 0..15
            int c4  = lin & 31;               // 0..31
            *reinterpret_cast<float4*>(&Bs[row][c4 * 4]) =
                *reinterpret_cast<const float4*>(
                    &W[(size_t)(k0 + row) * DM + n0 + c4 * 4]);
        }
        __syncthreads();

#pragma unroll
        for (int k = 0; k < 16; k++) {
            float a[8], b[8];
            *reinterpret_cast<float4*>(&a[0]) = *reinterpret_cast<float4*>(&As[k][ty * 8]);
            *reinterpret_cast<float4*>(&a[4]) = *reinterpret_cast<float4*>(&As[k][ty * 8 + 4]);
            *reinterpret_cast<float4*>(&b[0]) = *reinterpret_cast<float4*>(&Bs[k][tx * 8]);
            *reinterpret_cast<float4*>(&b[4]) = *reinterpret_cast<float4*>(&Bs[k][tx * 8 + 4]);
#pragma unroll
            for (int i = 0; i < 8; i++)
#pragma unroll
                for (int j = 0; j < 8; j++)
                    acc[i][j] = fmaf(a[i], b[j], acc[i][j]);
        }
        __syncthreads();
    }

    // Epilogue
#pragma unroll
    for (int i = 0; i < 8; i++) {
        int m = m0 + ty * 8 + i;
#pragma unroll
        for (int j = 0; j < 8; j++) {
            int n = n0 + tx * 8 + j;
            float val = acc[i][j] + bias[n];
            if (SCATTER) {
                int bb = m >> 11;        // / TSEQ
                int t  = m & 2047;
                int hh = n >> 6;         // / HD
                int dd = n & 63;
                out[((((size_t)bb * NH + hh) * TSEQ) + t) * HD + dd] = val;
            } else {
                out[(size_t)m * DM + n] = val;
            }
        }
    }
}

// ---------------------------------------------------------------------------
// Causal flash attention, fp32. One block = (bh, 64-row q-tile).
// 256 threads, 4x4 microtiles. Online softmax, P staged via SMEM.
// ---------------------------------------------------------------------------
__global__ void __launch_bounds__(256)
attn(const float* __restrict__ Q, const float* __restrict__ K,
     const float* __restrict__ V, float* __restrict__ ctx)
{
    extern __shared__ float sm[];
    float* Qs = sm;                 // [64][64]
    float* Ks = Qs + 64 * 64;       // [64][68]  (pad 68: stride = 17 quads, odd)
    float* Vs = Ks + 64 * 68;       // [64][64]
    float* Ps = Vs + 64 * 64;       // [64][65]

    const int qt  = gridDim.x - 1 - blockIdx.x;   // biggest tiles first
    const int bh  = blockIdx.y;
    const int tid = threadIdx.x;
    const int tx  = tid & 15;
    const int ty  = tid >> 4;
    const int q0  = qt * 64;
    const int r0  = ty * 4;

    const float* Qb = Q + (size_t)bh * TSEQ * HD;
    const float* Kb = K + (size_t)bh * TSEQ * HD;
    const float* Vb = V + (size_t)bh * TSEQ * HD;

    // Load Q tile once
#pragma unroll
    for (int i = 0; i < 4; i++) {
        int lin = tid + i * 256;
        int r = lin >> 4, dq = lin & 15;
        *reinterpret_cast<float4*>(&Qs[r * 64 + dq * 4]) =
            *reinterpret_cast<const float4*>(&Qb[(size_t)(q0 + r) * HD + dq * 4]);
    }

    float o[4][4];
#pragma unroll
    for (int i = 0; i < 4; i++)
#pragma unroll
        for (int j = 0; j < 4; j++) o[i][j] = 0.f;
    float mr[4], lr[4];
#pragma unroll
    for (int i = 0; i < 4; i++) { mr[i] = -1e30f; lr[i] = 0.f; }

    for (int kt = 0; kt <= qt; kt++) {
        const int k0 = kt * 64;
        __syncthreads();   // protect Ks/Vs/Ps from previous iter (also covers Qs load)
#pragma unroll
        for (int i = 0; i < 4; i++) {
            int lin = tid + i * 256;
            int r = lin >> 4, dq = lin & 15;
            *reinterpret_cast<float4*>(&Ks[r * 68 + dq * 4]) =
                *reinterpret_cast<const float4*>(&Kb[(size_t)(k0 + r) * HD + dq * 4]);
            *reinterpret_cast<float4*>(&Vs[r * 64 + dq * 4]) =
                *reinterpret_cast<const float4*>(&Vb[(size_t)(k0 + r) * HD + dq * 4]);
        }
        __syncthreads();

        // S = Q K^T   (rows r0..r0+3, cols tx + 16j)
        float s[4][4];
#pragma unroll
        for (int i = 0; i < 4; i++)
#pragma unroll
            for (int j = 0; j < 4; j++) s[i][j] = 0.f;

        for (int d = 0; d < 64; d += 4) {
            float4 qv[4], kv[4];
#pragma unroll
            for (int i = 0; i < 4; i++)
                qv[i] = *reinterpret_cast<const float4*>(&Qs[(r0 + i) * 64 + d]);
#pragma unroll
            for (int j = 0; j < 4; j++)
                kv[j] = *reinterpret_cast<const float4*>(&Ks[(tx + 16 * j) * 68 + d]);
#pragma unroll
            for (int i = 0; i < 4; i++)
#pragma unroll
                for (int j = 0; j < 4; j++) {
                    s[i][j] = fmaf(qv[i].x, kv[j].x, s[i][j]);
                    s[i][j] = fmaf(qv[i].y, kv[j].y, s[i][j]);
                    s[i][j] = fmaf(qv[i].z, kv[j].z, s[i][j]);
                    s[i][j] = fmaf(qv[i].w, kv[j].w, s[i][j]);
                }
        }

        const bool diag = (kt == qt);
#pragma unroll
        for (int i = 0; i < 4; i++)
#pragma unroll
            for (int j = 0; j < 4; j++) {
                float v = s[i][j] * 0.125f;                 // 1/sqrt(64)
                if (diag && (tx + 16 * j > r0 + i)) v = -1e30f;
                s[i][j] = v;
            }

        // Online softmax per row (reduce across the 16 tx lanes, width-16 shuffles)
#pragma unroll
        for (int i = 0; i < 4; i++) {
            float rmax = fmaxf(fmaxf(s[i][0], s[i][1]), fmaxf(s[i][2], s[i][3]));
#pragma unroll
            for (int off = 8; off > 0; off >>= 1)
                rmax = fmaxf(rmax, __shfl_xor_sync(0xffffffffu, rmax, off, 16));
            float mn    = fmaxf(mr[i], rmax);
            float alpha = __expf(mr[i] - mn);
            float rs = 0.f;
#pragma unroll
            for (int j = 0; j < 4; j++) {
                float p = __expf(s[i][j] - mn);
                rs += p;
                Ps[(r0 + i) * 65 + tx + 16 * j] = p;
            }
#pragma unroll
            for (int off = 8; off > 0; off >>= 1)
                rs += __shfl_xor_sync(0xffffffffu, rs, off, 16);
            lr[i] = lr[i] * alpha + rs;
            mr[i] = mn;
#pragma unroll
            for (int j = 0; j < 4; j++) o[i][j] *= alpha;
        }
        __syncthreads();   // Ps visible to all

        // O += P @ V   (output cols e = tx*4 + j)
#pragma unroll 4
        for (int c = 0; c < 64; c++) {
            float4 vv = *reinterpret_cast<const float4*>(&Vs[c * 64 + tx * 4]);
            float p0 = Ps[(r0 + 0) * 65 + c];
            float p1 = Ps[(r0 + 1) * 65 + c];
            float p2 = Ps[(r0 + 2) * 65 + c];
            float p3 = Ps[(r0 + 3) * 65 + c];
            o[0][0] = fmaf(p0, vv.x, o[0][0]); o[0][1] = fmaf(p0, vv.y, o[0][1]);
            o[0][2] = fmaf(p0, vv.z, o[0][2]); o[0][3] = fmaf(p0, vv.w, o[0][3]);
            o[1][0] = fmaf(p1, vv.x, o[1][0]); o[1][1] = fmaf(p1, vv.y, o[1][1]);
            o[1][2] = fmaf(p1, vv.z, o[1][2]); o[1][3] = fmaf(p1, vv.w, o[1][3]);
            o[2][0] = fmaf(p2, vv.x, o[2][0]); o[2][1] = fmaf(p2, vv.y, o[2][1]);
            o[2][2] = fmaf(p2, vv.z, o[2][2]); o[2][3] = fmaf(p2, vv.w, o[2][3]);
            o[3][0] = fmaf(p3, vv.x, o[3][0]); o[3][1] = fmaf(p3, vv.y, o[3][1]);
            o[3][2] = fmaf(p3, vv.z, o[3][2]); o[3][3] = fmaf(p3, vv.w, o[3][3]);
        }
    }

    // Write ctx[b, t, h*64 + e]
    const int b = bh >> 4;
    const int h = bh & 15;
#pragma unroll
    for (int i = 0; i < 4; i++) {
        float inv = 1.0f / lr[i];
        int t = q0 + r0 + i;
        float4 r;
        r.x = o[i][0] * inv; r.y = o[i][1] * inv;
        r.z = o[i][2] * inv; r.w = o[i][3] * inv;
        *reinterpret_cast<float4*>(
            &ctx[((size_t)(b * TSEQ + t)) * DM + h * HD + tx * 4]) = r;
    }
}

// ---------------------------------------------------------------------------
extern "C" void kernel_launch(void* const* d_in, const int* in_sizes, int n_in,
                              void* d_out, int out_size)
{
    const float* q  = (const float*)d_in[0];
    const float* k  = (const float*)d_in[1];
    const float* v  = (const float*)d_in[2];
    const float* wq = (const float*)d_in[3];
    const float* bq = (const float*)d_in[4];
    const float* wk = (const float*)d_in[5];
    const float* bk = (const float*)d_in[6];
    const float* wv = (const float*)d_in[7];
    const float* bv = (const float*)d_in[8];
    const float* wo = (const float*)d_in[9];
    const float* bo = (const float*)d_in[10];

    float *Qp, *Kp, *Vp, *Cp;
    cudaGetSymbolAddress((void**)&Qp, g_Q);
    cudaGetSymbolAddress((void**)&Kp, g_K);
    cudaGetSymbolAddress((void**)&Vp, g_V);
    cudaGetSymbolAddress((void**)&Cp, g_ctx);

    const int smem_attn = (64 * 64 + 64 * 68 + 64 * 64 + 64 * 65) * (int)sizeof(float);
    cudaFuncSetAttribute(attn, cudaFuncAttributeMaxDynamicSharedMemorySize, smem_attn);

    dim3 blk(256);
    dim3 gproj(DM / 128, MROWS / 128);   // (8, 64)

    gemm_bias<1><<<gproj, blk>>>(q, wq, bq, Qp);
    gemm_bias<1><<<gproj, blk>>>(k, wk, bk, Kp);
    gemm_bias<1><<<gproj, blk>>>(v, wv, bv, Vp);

    attn<<<dim3(TSEQ / 64, BSZ * NH), blk, smem_attn>>>(Qp, Kp, Vp, Cp);

    gemm_bias<0><<<gproj, blk>>>(Cp, wo, bo, (float*)d_out);
}

// round 7
// speedup vs baseline: 1.4078x; 1.4078x over previous
#include <cuda_runtime.h>
#include <cuda_bf16.h>
#include <cstdint>

#define DM   1024
#define NH   16
#define HD   64
#define BSZ  4
#define TSEQ 2048
#define MROWS (BSZ * TSEQ)   // 8192
#define K2   2048            // stored split K dimension (hi|lo)

// ---------------------------------------------------------------------------
// Scratch (allocation-free rule: __device__ globals)
// ---------------------------------------------------------------------------
__device__ float g_Q[(size_t)BSZ * NH * TSEQ * HD];   // [B,H,T,hd]
__device__ float g_K[(size_t)BSZ * NH * TSEQ * HD];
__device__ float g_V[(size_t)BSZ * NH * TSEQ * HD];
__device__ float g_ctx[(size_t)MROWS * DM];           // [B,T,D]
__device__ __align__(16) __nv_bfloat16 g_A2[(size_t)MROWS * K2];  // [M, hi|lo]
__device__ __align__(16) __nv_bfloat16 g_W2[(size_t)DM * K2];     // [N, hi|lo] (W^T)

// ---------------------------------------------------------------------------
// PTX helpers: ldmatrix / mma.sync / cp.async (legal on plain sm_100)
// ---------------------------------------------------------------------------
__device__ __forceinline__ uint32_t smem_to_u32(const void* p) {
    uint32_t a;
    asm("{ .reg .u64 t; cvta.to.shared.u64 t, %1; cvt.u32.u64 %0, t; }"
        : "=r"(a) : "l"(p));
    return a;
}
__device__ __forceinline__ void ldmatrix_x4(uint32_t* r, uint32_t addr) {
    asm volatile("ldmatrix.sync.aligned.m8n8.x4.shared.b16 {%0,%1,%2,%3}, [%4];"
        : "=r"(r[0]), "=r"(r[1]), "=r"(r[2]), "=r"(r[3]) : "r"(addr));
}
__device__ __forceinline__ void ldmatrix_x2(uint32_t* r, uint32_t addr) {
    asm volatile("ldmatrix.sync.aligned.m8n8.x2.shared.b16 {%0,%1}, [%2];"
        : "=r"(r[0]), "=r"(r[1]) : "r"(addr));
}
__device__ __forceinline__ void mma_16816(float* d, const uint32_t* a, const uint32_t* b) {
    asm volatile(
        "mma.sync.aligned.m16n8k16.row.col.f32.bf16.bf16.f32 "
        "{%0,%1,%2,%3}, {%4,%5,%6,%7}, {%8,%9}, {%0,%1,%2,%3};"
        : "+f"(d[0]), "+f"(d[1]), "+f"(d[2]), "+f"(d[3])
        : "r"(a[0]), "r"(a[1]), "r"(a[2]), "r"(a[3]), "r"(b[0]), "r"(b[1]));
}
#define CP_ASYNC16(dst, src) \
    asm volatile("cp.async.cg.shared.global [%0], [%1], 16;" \
        :: "r"(dst), "l"(src) : "memory")
#define CP_COMMIT() asm volatile("cp.async.commit_group;" ::: "memory")
#define CP_WAIT(n)  asm volatile("cp.async.wait_group %0;" :: "n"(n) : "memory")

// ---------------------------------------------------------------------------
// Split kernels: fp32 -> bf16 hi|lo
// ---------------------------------------------------------------------------
__global__ void __launch_bounds__(256)
split_act(const float4* __restrict__ x, __nv_bfloat162* __restrict__ A2, int n4)
{
    int i = blockIdx.x * blockDim.x + threadIdx.x;
    if (i >= n4) return;
    float4 v = x[i];
    int m  = i >> 8;            // 256 float4 per 1024-col row
    int kq = i & 255;
    __nv_bfloat162* hi = A2 + (size_t)m * (K2 / 2) + kq * 2;
    __nv_bfloat162* lo = hi + DM / 2;     // +1024 bf16
    __nv_bfloat16 hx = __float2bfloat16(v.x);
    __nv_bfloat16 hy = __float2bfloat16(v.y);
    __nv_bfloat16 hz = __float2bfloat16(v.z);
    __nv_bfloat16 hw = __float2bfloat16(v.w);
    hi[0] = __halves2bfloat162(hx, hy);
    hi[1] = __halves2bfloat162(hz, hw);
    lo[0] = __halves2bfloat162(__float2bfloat16(v.x - __bfloat162float(hx)),
                               __float2bfloat16(v.y - __bfloat162float(hy)));
    lo[1] = __halves2bfloat162(__float2bfloat16(v.z - __bfloat162float(hz)),
                               __float2bfloat16(v.w - __bfloat162float(hw)));
}

// W[K,N] fp32 -> W2[N, hi|lo] bf16 (transposed)
__global__ void __launch_bounds__(256)
split_wT(const float* __restrict__ w, __nv_bfloat16* __restrict__ W2)
{
    __shared__ float t[32][33];
    const int k0 = blockIdx.y * 32, n0 = blockIdx.x * 32;
    const int tx = threadIdx.x, ty = threadIdx.y;   // (32, 8)
#pragma unroll
    for (int i = 0; i < 32; i += 8)
        t[ty + i][tx] = w[(size_t)(k0 + ty + i) * DM + n0 + tx];
    __syncthreads();
#pragma unroll
    for (int i = 0; i < 32; i += 8) {
        float v = t[tx][ty + i];                    // w[k0+tx][n0+ty+i]
        __nv_bfloat16 h = __float2bfloat16(v);
        size_t o = (size_t)(n0 + ty + i) * K2 + k0 + tx;
        W2[o]      = h;
        W2[o + DM] = __float2bfloat16(v - __bfloat162float(h));
    }
}

// ---------------------------------------------------------------------------
// HMMA GEMM with 3-term split via k-tile remap:
//   kt in [0,32):  A_hi(k) x W_hi(k)
//   kt in [32,64): A_hi(k) x W_lo(k)
//   kt in [64,96): A_lo(k) x W_hi(k)
// => C = A_hi*W_hi + A_hi*W_lo + A_lo*W_hi  (drops only A_lo*W_lo ~ 2^-18)
// 128x128x32 tiles, 256 thr (2x4 warps, 64x32 warp tile), cp.async 2-stage.
// ---------------------------------------------------------------------------
#define BM 128
#define BN 128
#define BK 32
#define LDT 40                          // padded smem row (bf16)
#define TILE_B (BM * LDT * 2)           // 10240 bytes per tile buffer
#define NKT 96                          // 3 x 32 k-tiles

__device__ __forceinline__ int a_koff(int kt) {   // A column base for k-tile
    return ((kt >= 64) ? DM : 0) + (kt & 31) * BK;
}
__device__ __forceinline__ int w_koff(int kt) {   // W column base for k-tile
    return ((kt >= 32 && kt < 64) ? DM : 0) + (kt & 31) * BK;
}

template <int SCATTER>
__global__ void __launch_bounds__(256)
gemm_hmma(const __nv_bfloat16* __restrict__ A2, const __nv_bfloat16* __restrict__ W2,
          const float* __restrict__ bias, float* __restrict__ out)
{
    __shared__ __align__(16) __nv_bfloat16 As[2][BM][LDT];
    __shared__ __align__(16) __nv_bfloat16 Bs[2][BN][LDT];

    const int tid  = threadIdx.x;
    const int wid  = tid >> 5;
    const int lane = tid & 31;
    const int warp_m = wid >> 2;        // 0..1
    const int warp_n = wid & 3;         // 0..3
    const int m0 = blockIdx.y * BM;
    const int n0 = blockIdx.x * BN;

    const uint32_t sA = smem_to_u32(As);
    const uint32_t sB = smem_to_u32(Bs);

    float acc[4][4][4];
#pragma unroll
    for (int i = 0; i < 4; i++)
#pragma unroll
        for (int j = 0; j < 4; j++)
#pragma unroll
            for (int c = 0; c < 4; c++) acc[i][j][c] = 0.f;

    // ---- prefetch k-tile 0
    {
        const int ka = a_koff(0), kw = w_koff(0);
#pragma unroll
        for (int i = 0; i < 2; i++) {
            int c = tid + i * 256;       // 0..511
            int r = c >> 2, q = c & 3;
            CP_ASYNC16(sA + r * 80 + q * 16,
                       A2 + (size_t)(m0 + r) * K2 + ka + q * 8);
            CP_ASYNC16(sB + r * 80 + q * 16,
                       W2 + (size_t)(n0 + r) * K2 + kw + q * 8);
        }
        CP_COMMIT();
    }

    for (int kt = 0; kt < NKT; ++kt) {
        const int buf = kt & 1;
        if (kt + 1 < NKT) {
            const int nb = (kt + 1) & 1;
            const int ka = a_koff(kt + 1), kw = w_koff(kt + 1);
#pragma unroll
            for (int i = 0; i < 2; i++) {
                int c = tid + i * 256;
                int r = c >> 2, q = c & 3;
                CP_ASYNC16(sA + nb * TILE_B + r * 80 + q * 16,
                           A2 + (size_t)(m0 + r) * K2 + ka + q * 8);
                CP_ASYNC16(sB + nb * TILE_B + r * 80 + q * 16,
                           W2 + (size_t)(n0 + r) * K2 + kw + q * 8);
            }
            CP_COMMIT();
            CP_WAIT(1);
        } else {
            CP_WAIT(0);
        }
        __syncthreads();

        const uint32_t sAb = sA + buf * TILE_B;
        const uint32_t sBb = sB + buf * TILE_B;
#pragma unroll
        for (int kf = 0; kf < 2; ++kf) {
            uint32_t af[4][4], bf[4][2];
#pragma unroll
            for (int mf = 0; mf < 4; ++mf) {
                uint32_t addr = sAb +
                    ((warp_m * 64 + mf * 16 + (lane & 15)) * LDT
                     + kf * 16 + (lane >> 4) * 8) * 2;
                ldmatrix_x4(af[mf], addr);
            }
#pragma unroll
            for (int nf = 0; nf < 4; ++nf) {
                uint32_t addr = sBb +
                    ((warp_n * 32 + nf * 8 + (lane & 7)) * LDT
                     + kf * 16 + ((lane >> 3) & 1) * 8) * 2;
                ldmatrix_x2(bf[nf], addr);
            }
#pragma unroll
            for (int mf = 0; mf < 4; ++mf)
#pragma unroll
                for (int nf = 0; nf < 4; ++nf)
                    mma_16816(acc[mf][nf], af[mf], bf[nf]);
        }
        __syncthreads();   // all warps done with buf before it is overwritten
    }

    // ---- epilogue: bias + (optional) head scatter
    const int grp = lane >> 2;          // 0..7
    const int qd  = lane & 3;           // 0..3
#pragma unroll
    for (int mf = 0; mf < 4; ++mf) {
#pragma unroll
        for (int nf = 0; nf < 4; ++nf) {
            int m = m0 + warp_m * 64 + mf * 16 + grp;
            int n = n0 + warp_n * 32 + nf * 8 + qd * 2;
            float b0 = bias[n], b1 = bias[n + 1];
            float2 v0 = make_float2(acc[mf][nf][0] + b0, acc[mf][nf][1] + b1);
            float2 v1 = make_float2(acc[mf][nf][2] + b0, acc[mf][nf][3] + b1);
            if (SCATTER) {
                int bb = m >> 11, t = m & 2047;
                int hh = n >> 6,  dd = n & 63;
                size_t base = (((size_t)bb * NH + hh) * TSEQ) * HD + dd;
                *reinterpret_cast<float2*>(out + base + (size_t)t * HD) = v0;
                *reinterpret_cast<float2*>(out + base + (size_t)(t + 8) * HD) = v1;
            } else {
                *reinterpret_cast<float2*>(out + (size_t)m * DM + n) = v0;
                *reinterpret_cast<float2*>(out + (size_t)(m + 8) * DM + n) = v1;
            }
        }
    }
}

// ---------------------------------------------------------------------------
// Causal flash attention, fp32 (unchanged — proven; next round's target)
// ---------------------------------------------------------------------------
__global__ void __launch_bounds__(256)
attn(const float* __restrict__ Q, const float* __restrict__ K,
     const float* __restrict__ V, float* __restrict__ ctx)
{
    extern __shared__ float sm[];
    float* Qs = sm;                 // [64][64]
    float* Ks = Qs + 64 * 64;       // [64][68]
    float* Vs = Ks + 64 * 68;       // [64][64]
    float* Ps = Vs + 64 * 64;       // [64][65]

    const int qt  = gridDim.x - 1 - blockIdx.x;
    const int bh  = blockIdx.y;
    const int tid = threadIdx.x;
    const int tx  = tid & 15;
    const int ty  = tid >> 4;
    const int q0  = qt * 64;
    const int r0  = ty * 4;

    const float* Qb = Q + (size_t)bh * TSEQ * HD;
    const float* Kb = K + (size_t)bh * TSEQ * HD;
    const float* Vb = V + (size_t)bh * TSEQ * HD;

#pragma unroll
    for (int i = 0; i < 4; i++) {
        int lin = tid + i * 256;
        int r = lin >> 4, dq = lin & 15;
        *reinterpret_cast<float4*>(&Qs[r * 64 + dq * 4]) =
            *reinterpret_cast<const float4*>(&Qb[(size_t)(q0 + r) * HD + dq * 4]);
    }

    float o[4][4];
#pragma unroll
    for (int i = 0; i < 4; i++)
#pragma unroll
        for (int j = 0; j < 4; j++) o[i][j] = 0.f;
    float mr[4], lr[4];
#pragma unroll
    for (int i = 0; i < 4; i++) { mr[i] = -1e30f; lr[i] = 0.f; }

    for (int kt = 0; kt <= qt; kt++) {
        const int k0 = kt * 64;
        __syncthreads();
#pragma unroll
        for (int i = 0; i < 4; i++) {
            int lin = tid + i * 256;
            int r = lin >> 4, dq = lin & 15;
            *reinterpret_cast<float4*>(&Ks[r * 68 + dq * 4]) =
                *reinterpret_cast<const float4*>(&Kb[(size_t)(k0 + r) * HD + dq * 4]);
            *reinterpret_cast<float4*>(&Vs[r * 64 + dq * 4]) =
                *reinterpret_cast<const float4*>(&Vb[(size_t)(k0 + r) * HD + dq * 4]);
        }
        __syncthreads();

        float s[4][4];
#pragma unroll
        for (int i = 0; i < 4; i++)
#pragma unroll
            for (int j = 0; j < 4; j++) s[i][j] = 0.f;

        for (int d = 0; d < 64; d += 4) {
            float4 qv[4], kv[4];
#pragma unroll
            for (int i = 0; i < 4; i++)
                qv[i] = *reinterpret_cast<const float4*>(&Qs[(r0 + i) * 64 + d]);
#pragma unroll
            for (int j = 0; j < 4; j++)
                kv[j] = *reinterpret_cast<const float4*>(&Ks[(tx + 16 * j) * 68 + d]);
#pragma unroll
            for (int i = 0; i < 4; i++)
#pragma unroll
                for (int j = 0; j < 4; j++) {
                    s[i][j] = fmaf(qv[i].x, kv[j].x, s[i][j]);
                    s[i][j] = fmaf(qv[i].y, kv[j].y, s[i][j]);
                    s[i][j] = fmaf(qv[i].z, kv[j].z, s[i][j]);
                    s[i][j] = fmaf(qv[i].w, kv[j].w, s[i][j]);
                }
        }

        const bool diag = (kt == qt);
#pragma unroll
        for (int i = 0; i < 4; i++)
#pragma unroll
            for (int j = 0; j < 4; j++) {
                float v = s[i][j] * 0.125f;
                if (diag && (tx + 16 * j > r0 + i)) v = -1e30f;
                s[i][j] = v;
            }

#pragma unroll
        for (int i = 0; i < 4; i++) {
            float rmax = fmaxf(fmaxf(s[i][0], s[i][1]), fmaxf(s[i][2], s[i][3]));
#pragma unroll
            for (int off = 8; off > 0; off >>= 1)
                rmax = fmaxf(rmax, __shfl_xor_sync(0xffffffffu, rmax, off, 16));
            float mn    = fmaxf(mr[i], rmax);
            float alpha = __expf(mr[i] - mn);
            float rs = 0.f;
#pragma unroll
            for (int j = 0; j < 4; j++) {
                float p = __expf(s[i][j] - mn);
                rs += p;
                Ps[(r0 + i) * 65 + tx + 16 * j] = p;
            }
#pragma unroll
            for (int off = 8; off > 0; off >>= 1)
                rs += __shfl_xor_sync(0xffffffffu, rs, off, 16);
            lr[i] = lr[i] * alpha + rs;
            mr[i] = mn;
#pragma unroll
            for (int j = 0; j < 4; j++) o[i][j] *= alpha;
        }
        __syncthreads();

#pragma unroll 4
        for (int c = 0; c < 64; c++) {
            float4 vv = *reinterpret_cast<const float4*>(&Vs[c * 64 + tx * 4]);
            float p0 = Ps[(r0 + 0) * 65 + c];
            float p1 = Ps[(r0 + 1) * 65 + c];
            float p2 = Ps[(r0 + 2) * 65 + c];
            float p3 = Ps[(r0 + 3) * 65 + c];
            o[0][0] = fmaf(p0, vv.x, o[0][0]); o[0][1] = fmaf(p0, vv.y, o[0][1]);
            o[0][2] = fmaf(p0, vv.z, o[0][2]); o[0][3] = fmaf(p0, vv.w, o[0][3]);
            o[1][0] = fmaf(p1, vv.x, o[1][0]); o[1][1] = fmaf(p1, vv.y, o[1][1]);
            o[1][2] = fmaf(p1, vv.z, o[1][2]); o[1][3] = fmaf(p1, vv.w, o[1][3]);
            o[2][0] = fmaf(p2, vv.x, o[2][0]); o[2][1] = fmaf(p2, vv.y, o[2][1]);
            o[2][2] = fmaf(p2, vv.z, o[2][2]); o[2][3] = fmaf(p2, vv.w, o[2][3]);
            o[3][0] = fmaf(p3, vv.x, o[3][0]); o[3][1] = fmaf(p3, vv.y, o[3][1]);
            o[3][2] = fmaf(p3, vv.z, o[3][2]); o[3][3] = fmaf(p3, vv.w, o[3][3]);
        }
    }

    const int b = bh >> 4;
    const int h = bh & 15;
#pragma unroll
    for (int i = 0; i < 4; i++) {
        float inv = 1.0f / lr[i];
        int t = q0 + r0 + i;
        float4 r;
        r.x = o[i][0] * inv; r.y = o[i][1] * inv;
        r.z = o[i][2] * inv; r.w = o[i][3] * inv;
        *reinterpret_cast<float4*>(
            &ctx[((size_t)(b * TSEQ + t)) * DM + h * HD + tx * 4]) = r;
    }
}

// ---------------------------------------------------------------------------
extern "C" void kernel_launch(void* const* d_in, const int* in_sizes, int n_in,
                              void* d_out, int out_size)
{
    const float* q  = (const float*)d_in[0];
    const float* k  = (const float*)d_in[1];
    const float* v  = (const float*)d_in[2];
    const float* wq = (const float*)d_in[3];
    const float* bq = (const float*)d_in[4];
    const float* wk = (const float*)d_in[5];
    const float* bk = (const float*)d_in[6];
    const float* wv = (const float*)d_in[7];
    const float* bv = (const float*)d_in[8];
    const float* wo = (const float*)d_in[9];
    const float* bo = (const float*)d_in[10];

    float *Qp, *Kp, *Vp, *Cp;
    __nv_bfloat16 *A2p, *W2p;
    cudaGetSymbolAddress((void**)&Qp,  g_Q);
    cudaGetSymbolAddress((void**)&Kp,  g_K);
    cudaGetSymbolAddress((void**)&Vp,  g_V);
    cudaGetSymbolAddress((void**)&Cp,  g_ctx);
    cudaGetSymbolAddress((void**)&A2p, g_A2);
    cudaGetSymbolAddress((void**)&W2p, g_W2);

    const int smem_attn = (64 * 64 + 64 * 68 + 64 * 64 + 64 * 65) * (int)sizeof(float);
    cudaFuncSetAttribute(attn, cudaFuncAttributeMaxDynamicSharedMemorySize, smem_attn);

    const int n4 = MROWS * DM / 4;
    dim3 sblk(256), sgrid((n4 + 255) / 256);
    dim3 wgrid(DM / 32, DM / 32), wblk(32, 8);
    dim3 gblk(256), ggrid(DM / BN, MROWS / BM);   // (8, 64)

    // Q projection
    split_wT<<<wgrid, wblk>>>(wq, W2p);
    split_act<<<sgrid, sblk>>>((const float4*)q, (__nv_bfloat162*)A2p, n4);
    gemm_hmma<1><<<ggrid, gblk>>>(A2p, W2p, bq, Qp);
    // K projection
    split_wT<<<wgrid, wblk>>>(wk, W2p);
    split_act<<<sgrid, sblk>>>((const float4*)k, (__nv_bfloat162*)A2p, n4);
    gemm_hmma<1><<<ggrid, gblk>>>(A2p, W2p, bk, Kp);
    // V projection
    split_wT<<<wgrid, wblk>>>(wv, W2p);
    split_act<<<sgrid, sblk>>>((const float4*)v, (__nv_bfloat162*)A2p, n4);
    gemm_hmma<1><<<ggrid, gblk>>>(A2p, W2p, bv, Vp);

    // attention
    attn<<<dim3(TSEQ / 64, BSZ * NH), dim3(256), smem_attn>>>(Qp, Kp, Vp, Cp);

    // output projection
    split_wT<<<wgrid, wblk>>>(wo, W2p);
    split_act<<<sgrid, sblk>>>((const float4*)Cp, (__nv_bfloat162*)A2p, n4);
    gemm_hmma<0><<<ggrid, gblk>>>(A2p, W2p, bo, (float*)d_out);
}

// round 8
// speedup vs baseline: 2.6374x; 1.8735x over previous
#include <cuda_runtime.h>
#include <cuda_bf16.h>
#include <cuda_fp16.h>
#include <cstdint>

#define DM   1024
#define NH   16
#define HD   64
#define BSZ  4
#define TSEQ 2048
#define MROWS (BSZ * TSEQ)   // 8192
#define K2   2048            // stored split K dimension (hi|lo)

// ---------------------------------------------------------------------------
// Scratch (allocation-free rule: __device__ globals)
// ---------------------------------------------------------------------------
__device__ __align__(16) __half g_Qh[(size_t)BSZ * NH * TSEQ * HD];  // [B,H,T,hd], pre-scaled 1/8
__device__ __align__(16) __half g_Kh[(size_t)BSZ * NH * TSEQ * HD];
__device__ __align__(16) __half g_Vh[(size_t)BSZ * NH * TSEQ * HD];
__device__ float g_ctx[(size_t)MROWS * DM];                          // [B,T,D]
__device__ __align__(16) __nv_bfloat16 g_A2[(size_t)MROWS * K2];     // [M, hi|lo]
__device__ __align__(16) __nv_bfloat16 g_W2[(size_t)DM * K2];        // [N, hi|lo] (W^T)

// ---------------------------------------------------------------------------
// PTX helpers (legal on plain sm_100)
// ---------------------------------------------------------------------------
__device__ __forceinline__ uint32_t smem_to_u32(const void* p) {
    uint32_t a;
    asm("{ .reg .u64 t; cvta.to.shared.u64 t, %1; cvt.u32.u64 %0, t; }"
        : "=r"(a) : "l"(p));
    return a;
}
__device__ __forceinline__ void ldmatrix_x4(uint32_t* r, uint32_t addr) {
    asm volatile("ldmatrix.sync.aligned.m8n8.x4.shared.b16 {%0,%1,%2,%3}, [%4];"
        : "=r"(r[0]), "=r"(r[1]), "=r"(r[2]), "=r"(r[3]) : "r"(addr));
}
__device__ __forceinline__ void ldmatrix_x2(uint32_t* r, uint32_t addr) {
    asm volatile("ldmatrix.sync.aligned.m8n8.x2.shared.b16 {%0,%1}, [%2];"
        : "=r"(r[0]), "=r"(r[1]) : "r"(addr));
}
__device__ __forceinline__ void mma_bf16(float* d, const uint32_t* a, const uint32_t* b) {
    asm volatile(
        "mma.sync.aligned.m16n8k16.row.col.f32.bf16.bf16.f32 "
        "{%0,%1,%2,%3}, {%4,%5,%6,%7}, {%8,%9}, {%0,%1,%2,%3};"
        : "+f"(d[0]), "+f"(d[1]), "+f"(d[2]), "+f"(d[3])
        : "r"(a[0]), "r"(a[1]), "r"(a[2]), "r"(a[3]), "r"(b[0]), "r"(b[1]));
}
__device__ __forceinline__ void mma_f16(float* d, const uint32_t* a, const uint32_t* b) {
    asm volatile(
        "mma.sync.aligned.m16n8k16.row.col.f32.f16.f16.f32 "
        "{%0,%1,%2,%3}, {%4,%5,%6,%7}, {%8,%9}, {%0,%1,%2,%3};"
        : "+f"(d[0]), "+f"(d[1]), "+f"(d[2]), "+f"(d[3])
        : "r"(a[0]), "r"(a[1]), "r"(a[2]), "r"(a[3]), "r"(b[0]), "r"(b[1]));
}
#define CP_ASYNC16(dst, src) \
    asm volatile("cp.async.cg.shared.global [%0], [%1], 16;" \
        :: "r"(dst), "l"(src) : "memory")
#define CP_COMMIT() asm volatile("cp.async.commit_group;" ::: "memory")
#define CP_WAIT(n)  asm volatile("cp.async.wait_group %0;" :: "n"(n) : "memory")

__device__ __forceinline__ uint32_t pack_h2(float lo, float hi) {
    __half2 h = __floats2half2_rn(lo, hi);
    return *reinterpret_cast<uint32_t*>(&h);
}

// ---------------------------------------------------------------------------
// Split kernels: fp32 -> bf16 hi|lo
// ---------------------------------------------------------------------------
__global__ void __launch_bounds__(256)
split_act(const float4* __restrict__ x, __nv_bfloat162* __restrict__ A2, int n4)
{
    int i = blockIdx.x * blockDim.x + threadIdx.x;
    if (i >= n4) return;
    float4 v = x[i];
    int m  = i >> 8;
    int kq = i & 255;
    __nv_bfloat162* hi = A2 + (size_t)m * (K2 / 2) + kq * 2;
    __nv_bfloat162* lo = hi + DM / 2;
    __nv_bfloat16 hx = __float2bfloat16(v.x);
    __nv_bfloat16 hy = __float2bfloat16(v.y);
    __nv_bfloat16 hz = __float2bfloat16(v.z);
    __nv_bfloat16 hw = __float2bfloat16(v.w);
    hi[0] = __halves2bfloat162(hx, hy);
    hi[1] = __halves2bfloat162(hz, hw);
    lo[0] = __halves2bfloat162(__float2bfloat16(v.x - __bfloat162float(hx)),
                               __float2bfloat16(v.y - __bfloat162float(hy)));
    lo[1] = __halves2bfloat162(__float2bfloat16(v.z - __bfloat162float(hz)),
                               __float2bfloat16(v.w - __bfloat162float(hw)));
}

__global__ void __launch_bounds__(256)
split_wT(const float* __restrict__ w, __nv_bfloat16* __restrict__ W2)
{
    __shared__ float t[32][33];
    const int k0 = blockIdx.y * 32, n0 = blockIdx.x * 32;
    const int tx = threadIdx.x, ty = threadIdx.y;   // (32, 8)
#pragma unroll
    for (int i = 0; i < 32; i += 8)
        t[ty + i][tx] = w[(size_t)(k0 + ty + i) * DM + n0 + tx];
    __syncthreads();
#pragma unroll
    for (int i = 0; i < 32; i += 8) {
        float v = t[tx][ty + i];
        __nv_bfloat16 h = __float2bfloat16(v);
        size_t o = (size_t)(n0 + ty + i) * K2 + k0 + tx;
        W2[o]      = h;
        W2[o + DM] = __float2bfloat16(v - __bfloat162float(h));
    }
}

// ---------------------------------------------------------------------------
// HMMA GEMM, 3-term split via k-tile remap (R7, proven). OT = __half or float.
// ---------------------------------------------------------------------------
#define BM 128
#define BN 128
#define BK 32
#define LDT 40
#define TILE_B (BM * LDT * 2)
#define NKT 96

__device__ __forceinline__ int a_koff(int kt) {
    return ((kt >= 64) ? DM : 0) + (kt & 31) * BK;
}
__device__ __forceinline__ int w_koff(int kt) {
    return ((kt >= 32 && kt < 64) ? DM : 0) + (kt & 31) * BK;
}
__device__ __forceinline__ void store2(float* p, float x, float y) {
    *reinterpret_cast<float2*>(p) = make_float2(x, y);
}
__device__ __forceinline__ void store2(__half* p, float x, float y) {
    *reinterpret_cast<__half2*>(p) = __floats2half2_rn(x, y);
}

template <typename OT, int SCATTER>
__global__ void __launch_bounds__(256)
gemm_hmma(const __nv_bfloat16* __restrict__ A2, const __nv_bfloat16* __restrict__ W2,
          const float* __restrict__ bias, OT* __restrict__ out, float scale)
{
    __shared__ __align__(16) __nv_bfloat16 As[2][BM][LDT];
    __shared__ __align__(16) __nv_bfloat16 Bs[2][BN][LDT];

    const int tid  = threadIdx.x;
    const int wid  = tid >> 5;
    const int lane = tid & 31;
    const int warp_m = wid >> 2;
    const int warp_n = wid & 3;
    const int m0 = blockIdx.y * BM;
    const int n0 = blockIdx.x * BN;

    const uint32_t sA = smem_to_u32(As);
    const uint32_t sB = smem_to_u32(Bs);

    float acc[4][4][4];
#pragma unroll
    for (int i = 0; i < 4; i++)
#pragma unroll
        for (int j = 0; j < 4; j++)
#pragma unroll
            for (int c = 0; c < 4; c++) acc[i][j][c] = 0.f;

    {
        const int ka = a_koff(0), kw = w_koff(0);
#pragma unroll
        for (int i = 0; i < 2; i++) {
            int c = tid + i * 256;
            int r = c >> 2, q = c & 3;
            CP_ASYNC16(sA + r * 80 + q * 16, A2 + (size_t)(m0 + r) * K2 + ka + q * 8);
            CP_ASYNC16(sB + r * 80 + q * 16, W2 + (size_t)(n0 + r) * K2 + kw + q * 8);
        }
        CP_COMMIT();
    }

    for (int kt = 0; kt < NKT; ++kt) {
        const int buf = kt & 1;
        if (kt + 1 < NKT) {
            const int nb = (kt + 1) & 1;
            const int ka = a_koff(kt + 1), kw = w_koff(kt + 1);
#pragma unroll
            for (int i = 0; i < 2; i++) {
                int c = tid + i * 256;
                int r = c >> 2, q = c & 3;
                CP_ASYNC16(sA + nb * TILE_B + r * 80 + q * 16,
                           A2 + (size_t)(m0 + r) * K2 + ka + q * 8);
                CP_ASYNC16(sB + nb * TILE_B + r * 80 + q * 16,
                           W2 + (size_t)(n0 + r) * K2 + kw + q * 8);
            }
            CP_COMMIT();
            CP_WAIT(1);
        } else {
            CP_WAIT(0);
        }
        __syncthreads();

        const uint32_t sAb = sA + buf * TILE_B;
        const uint32_t sBb = sB + buf * TILE_B;
#pragma unroll
        for (int kf = 0; kf < 2; ++kf) {
            uint32_t af[4][4], bf[4][2];
#pragma unroll
            for (int mf = 0; mf < 4; ++mf) {
                uint32_t addr = sAb +
                    ((warp_m * 64 + mf * 16 + (lane & 15)) * LDT
                     + kf * 16 + (lane >> 4) * 8) * 2;
                ldmatrix_x4(af[mf], addr);
            }
#pragma unroll
            for (int nf = 0; nf < 4; ++nf) {
                uint32_t addr = sBb +
                    ((warp_n * 32 + nf * 8 + (lane & 7)) * LDT
                     + kf * 16 + ((lane >> 3) & 1) * 8) * 2;
                ldmatrix_x2(bf[nf], addr);
            }
#pragma unroll
            for (int mf = 0; mf < 4; ++mf)
#pragma unroll
                for (int nf = 0; nf < 4; ++nf)
                    mma_bf16(acc[mf][nf], af[mf], bf[nf]);
        }
        __syncthreads();
    }

    const int grp = lane >> 2;
    const int qd  = lane & 3;
#pragma unroll
    for (int mf = 0; mf < 4; ++mf) {
#pragma unroll
        for (int nf = 0; nf < 4; ++nf) {
            int m = m0 + warp_m * 64 + mf * 16 + grp;
            int n = n0 + warp_n * 32 + nf * 8 + qd * 2;
            float b0 = bias[n], b1 = bias[n + 1];
            float x0 = (acc[mf][nf][0] + b0) * scale;
            float y0 = (acc[mf][nf][1] + b1) * scale;
            float x1 = (acc[mf][nf][2] + b0) * scale;
            float y1 = (acc[mf][nf][3] + b1) * scale;
            if (SCATTER) {
                int bb = m >> 11, t = m & 2047;
                int hh = n >> 6,  dd = n & 63;
                size_t base = (((size_t)bb * NH + hh) * TSEQ) * HD + dd;
                store2(out + base + (size_t)t * HD, x0, y0);
                store2(out + base + (size_t)(t + 8) * HD, x1, y1);
            } else {
                store2(out + (size_t)m * DM + n, x0, y0);
                store2(out + (size_t)(m + 8) * DM + n, x1, y1);
            }
        }
    }
}

// ---------------------------------------------------------------------------
// HMMA causal flash attention, fp16 operands / fp32 softmax+accum.
// 128 threads = 4 warps; warp owns 16 q-rows of a 64-row q-tile.
// ---------------------------------------------------------------------------
__global__ void __launch_bounds__(128)
attn_hmma(const __half* __restrict__ Q, const __half* __restrict__ K,
          const __half* __restrict__ V, float* __restrict__ ctx)
{
    __shared__ __align__(16) __half Qs[64][72];
    __shared__ __align__(16) __half Ks[64][72];
    __shared__ __align__(16) __half Vt[64][72];   // [dim][key] (transposed at fill)

    const int qt   = gridDim.x - 1 - blockIdx.x;  // biggest tiles first
    const int bh   = blockIdx.y;
    const int tid  = threadIdx.x;
    const int wid  = tid >> 5;
    const int lane = tid & 31;
    const int q0   = qt * 64;

    const __half* Qb = Q + (size_t)bh * TSEQ * HD;
    const __half* Kb = K + (size_t)bh * TSEQ * HD;
    const __half* Vb = V + (size_t)bh * TSEQ * HD;

    const uint32_t sQ = smem_to_u32(Qs);
    const uint32_t sK = smem_to_u32(Ks);
    const uint32_t sV = smem_to_u32(Vt);

    // ---- load Q tile (64 x 64 fp16)
#pragma unroll
    for (int it = 0; it < 4; ++it) {
        int lin = tid + it * 128;
        int r = lin >> 3, qd = lin & 7;
        *reinterpret_cast<float4*>(&Qs[r][qd * 8]) =
            *reinterpret_cast<const float4*>(&Qb[(size_t)(q0 + r) * HD + qd * 8]);
    }
    __syncthreads();

    // ---- hoist Q A-fragments (rows wid*16..+15, all 4 k16 chunks)
    uint32_t aq[4][4];
#pragma unroll
    for (int kc = 0; kc < 4; ++kc) {
        uint32_t addr = sQ + ((wid * 16 + (lane & 15)) * 72 + kc * 16 + 8 * (lane >> 4)) * 2;
        ldmatrix_x4(aq[kc], addr);
    }

    float o[8][4];
#pragma unroll
    for (int i = 0; i < 8; i++)
#pragma unroll
        for (int c = 0; c < 4; c++) o[i][c] = 0.f;
    float m_a = -1e30f, m_b = -1e30f, l_a = 0.f, l_b = 0.f;

    for (int kt = 0; kt <= qt; ++kt) {
        const int k0 = kt * 64;
        __syncthreads();   // previous iteration done with Ks/Vt
        // ---- fill K tile (row-major [key][dim])
#pragma unroll
        for (int it = 0; it < 4; ++it) {
            int lin = tid + it * 128;
            int r = lin >> 3, qd = lin & 7;
            *reinterpret_cast<float4*>(&Ks[r][qd * 8]) =
                *reinterpret_cast<const float4*>(&Kb[(size_t)(k0 + r) * HD + qd * 8]);
        }
        // ---- fill V transposed ([dim][key]), lane-staggered to avoid conflicts
#pragma unroll
        for (int it = 0; it < 4; ++it) {
            int lin = tid + it * 128;
            int key = lin >> 3, qd = lin & 7;
            float4 v = *reinterpret_cast<const float4*>(&Vb[(size_t)(k0 + key) * HD + qd * 8]);
            const __half* hv = reinterpret_cast<const __half*>(&v);
#pragma unroll
            for (int i = 0; i < 8; ++i) {
                int ii = (i + qd) & 7;
                Vt[qd * 8 + ii][key] = hv[ii];
            }
        }
        __syncthreads();

        // ---- S = Q K^T (warp's 16 rows x 64 keys), fp32 accum
        float s[8][4];
#pragma unroll
        for (int i = 0; i < 8; i++)
#pragma unroll
            for (int c = 0; c < 4; c++) s[i][c] = 0.f;
#pragma unroll
        for (int kc = 0; kc < 4; ++kc) {
#pragma unroll
            for (int j = 0; j < 4; ++j) {
                uint32_t bk[4];
                uint32_t addr = sK +
                    ((j * 16 + ((lane >> 4) << 3) + (lane & 7)) * 72
                     + kc * 16 + 8 * ((lane >> 3) & 1)) * 2;
                ldmatrix_x4(bk, addr);
                mma_f16(s[2 * j],     aq[kc], bk);
                mma_f16(s[2 * j + 1], aq[kc], bk + 2);
            }
        }

        // ---- causal mask on the diagonal tile
        if (kt == qt) {
            const int ra = wid * 16 + (lane >> 2);
#pragma unroll
            for (int nf = 0; nf < 8; ++nf) {
#pragma unroll
                for (int c = 0; c < 4; ++c) {
                    int key = nf * 8 + 2 * (lane & 3) + (c & 1);
                    int row = ra + 8 * (c >> 1);
                    if (key > row) s[nf][c] = -1e30f;
                }
            }
        }

        // ---- online softmax (rows ra = lane>>2, rb = ra+8 within warp tile)
        float mxa = -1e30f, mxb = -1e30f;
#pragma unroll
        for (int nf = 0; nf < 8; ++nf) {
            mxa = fmaxf(mxa, fmaxf(s[nf][0], s[nf][1]));
            mxb = fmaxf(mxb, fmaxf(s[nf][2], s[nf][3]));
        }
        mxa = fmaxf(mxa, __shfl_xor_sync(0xffffffffu, mxa, 1));
        mxa = fmaxf(mxa, __shfl_xor_sync(0xffffffffu, mxa, 2));
        mxb = fmaxf(mxb, __shfl_xor_sync(0xffffffffu, mxb, 1));
        mxb = fmaxf(mxb, __shfl_xor_sync(0xffffffffu, mxb, 2));
        float mna = fmaxf(m_a, mxa), mnb = fmaxf(m_b, mxb);
        float ala = __expf(m_a - mna), alb = __expf(m_b - mnb);
        float sa = 0.f, sb = 0.f;
#pragma unroll
        for (int nf = 0; nf < 8; ++nf) {
            s[nf][0] = __expf(s[nf][0] - mna);
            s[nf][1] = __expf(s[nf][1] - mna);
            s[nf][2] = __expf(s[nf][2] - mnb);
            s[nf][3] = __expf(s[nf][3] - mnb);
            sa += s[nf][0] + s[nf][1];
            sb += s[nf][2] + s[nf][3];
        }
        sa += __shfl_xor_sync(0xffffffffu, sa, 1);
        sa += __shfl_xor_sync(0xffffffffu, sa, 2);
        sb += __shfl_xor_sync(0xffffffffu, sb, 1);
        sb += __shfl_xor_sync(0xffffffffu, sb, 2);
        l_a = l_a * ala + sa;  m_a = mna;
        l_b = l_b * alb + sb;  m_b = mnb;
#pragma unroll
        for (int nf = 0; nf < 8; ++nf) {
            o[nf][0] *= ala; o[nf][1] *= ala;
            o[nf][2] *= alb; o[nf][3] *= alb;
        }

        // ---- O += P @ V  (P fragments repacked from S accumulators)
#pragma unroll
        for (int kc2 = 0; kc2 < 4; ++kc2) {
            uint32_t ap[4];
            ap[0] = pack_h2(s[2 * kc2][0],     s[2 * kc2][1]);
            ap[1] = pack_h2(s[2 * kc2][2],     s[2 * kc2][3]);
            ap[2] = pack_h2(s[2 * kc2 + 1][0], s[2 * kc2 + 1][1]);
            ap[3] = pack_h2(s[2 * kc2 + 1][2], s[2 * kc2 + 1][3]);
#pragma unroll
            for (int nf2 = 0; nf2 < 4; ++nf2) {
                uint32_t bv[4];
                uint32_t addr = sV +
                    ((nf2 * 16 + ((lane >> 4) << 3) + (lane & 7)) * 72
                     + kc2 * 16 + 8 * ((lane >> 3) & 1)) * 2;
                ldmatrix_x4(bv, addr);
                mma_f16(o[2 * nf2],     ap, bv);
                mma_f16(o[2 * nf2 + 1], ap, bv + 2);
            }
        }
    }

    // ---- write ctx[b, t, h*64 + d]
    const int b = bh >> 4;
    const int h = bh & 15;
    const int ta = q0 + wid * 16 + (lane >> 2);
    const int tb = ta + 8;
    const float inva = 1.0f / l_a;
    const float invb = 1.0f / l_b;
#pragma unroll
    for (int nf = 0; nf < 8; ++nf) {
        int col = h * HD + nf * 8 + 2 * (lane & 3);
        *reinterpret_cast<float2*>(&ctx[(size_t)(b * TSEQ + ta) * DM + col]) =
            make_float2(o[nf][0] * inva, o[nf][1] * inva);
        *reinterpret_cast<float2*>(&ctx[(size_t)(b * TSEQ + tb) * DM + col]) =
            make_float2(o[nf][2] * invb, o[nf][3] * invb);
    }
}

// ---------------------------------------------------------------------------
extern "C" void kernel_launch(void* const* d_in, const int* in_sizes, int n_in,
                              void* d_out, int out_size)
{
    const float* q  = (const float*)d_in[0];
    const float* k  = (const float*)d_in[1];
    const float* v  = (const float*)d_in[2];
    const float* wq = (const float*)d_in[3];
    const float* bq = (const float*)d_in[4];
    const float* wk = (const float*)d_in[5];
    const float* bk = (const float*)d_in[6];
    const float* wv = (const float*)d_in[7];
    const float* bv = (const float*)d_in[8];
    const float* wo = (const float*)d_in[9];
    const float* bo = (const float*)d_in[10];

    __half *Qp, *Kp, *Vp;
    float *Cp;
    __nv_bfloat16 *A2p, *W2p;
    cudaGetSymbolAddress((void**)&Qp,  g_Qh);
    cudaGetSymbolAddress((void**)&Kp,  g_Kh);
    cudaGetSymbolAddress((void**)&Vp,  g_Vh);
    cudaGetSymbolAddress((void**)&Cp,  g_ctx);
    cudaGetSymbolAddress((void**)&A2p, g_A2);
    cudaGetSymbolAddress((void**)&W2p, g_W2);

    const int n4 = MROWS * DM / 4;
    dim3 sblk(256), sgrid((n4 + 255) / 256);
    dim3 wgrid(DM / 32, DM / 32), wblk(32, 8);
    dim3 gblk(256), ggrid(DM / BN, MROWS / BM);   // (8, 64)

    // Q projection (pre-scaled by 1/sqrt(hd) = 0.125)
    split_wT<<<wgrid, wblk>>>(wq, W2p);
    split_act<<<sgrid, sblk>>>((const float4*)q, (__nv_bfloat162*)A2p, n4);
    gemm_hmma<__half, 1><<<ggrid, gblk>>>(A2p, W2p, bq, Qp, 0.125f);
    // K projection
    split_wT<<<wgrid, wblk>>>(wk, W2p);
    split_act<<<sgrid, sblk>>>((const float4*)k, (__nv_bfloat162*)A2p, n4);
    gemm_hmma<__half, 1><<<ggrid, gblk>>>(A2p, W2p, bk, Kp, 1.0f);
    // V projection
    split_wT<<<wgrid, wblk>>>(wv, W2p);
    split_act<<<sgrid, sblk>>>((const float4*)v, (__nv_bfloat162*)A2p, n4);
    gemm_hmma<__half, 1><<<ggrid, gblk>>>(A2p, W2p, bv, Vp, 1.0f);

    // attention (HMMA fp16)
    attn_hmma<<<dim3(TSEQ / 64, BSZ * NH), dim3(128)>>>(Qp, Kp, Vp, Cp);

    // output projection (fp32 out)
    split_wT<<<wgrid, wblk>>>(wo, W2p);
    split_act<<<sgrid, sblk>>>((const float4*)Cp, (__nv_bfloat162*)A2p, n4);
    gemm_hmma<float, 0><<<ggrid, gblk>>>(A2p, W2p, bo, (float*)d_out, 1.0f);
}

// round 9
// speedup vs baseline: 4.1124x; 1.5592x over previous
#include <cuda_runtime.h>
#include <cuda_bf16.h>
#include <cuda_fp16.h>
#include <cstdint>

#define DM   1024
#define NH   16
#define HD   64
#define BSZ  4
#define TSEQ 2048
#define MROWS (BSZ * TSEQ)   // 8192
#define K2   2048            // stored split K dimension (hi|lo)

// ---------------------------------------------------------------------------
// Scratch (allocation-free rule: __device__ globals)
// ---------------------------------------------------------------------------
__device__ __align__(16) __half g_Qh[(size_t)BSZ * NH * TSEQ * HD];  // [B,H,T,hd], pre-scaled 1/8
__device__ __align__(16) __half g_Kh[(size_t)BSZ * NH * TSEQ * HD];
__device__ __align__(16) __half g_Vh[(size_t)BSZ * NH * TSEQ * HD];
__device__ float g_ctx[(size_t)MROWS * DM];                          // [B,T,D]
__device__ __align__(16) __half g_Af[(size_t)MROWS * DM];            // fp16 activations
__device__ __align__(16) __half g_Wf[(size_t)DM * DM];               // fp16 W^T [N,K]
__device__ __align__(16) __nv_bfloat16 g_A2[(size_t)MROWS * K2];     // [M, hi|lo] (O proj)
__device__ __align__(16) __nv_bfloat16 g_W2[(size_t)DM * K2];        // [N, hi|lo] (O proj)

// ---------------------------------------------------------------------------
// PTX helpers (legal on plain sm_100)
// ---------------------------------------------------------------------------
__device__ __forceinline__ uint32_t smem_to_u32(const void* p) {
    uint32_t a;
    asm("{ .reg .u64 t; cvta.to.shared.u64 t, %1; cvt.u32.u64 %0, t; }"
        : "=r"(a) : "l"(p));
    return a;
}
__device__ __forceinline__ void ldmatrix_x4(uint32_t* r, uint32_t addr) {
    asm volatile("ldmatrix.sync.aligned.m8n8.x4.shared.b16 {%0,%1,%2,%3}, [%4];"
        : "=r"(r[0]), "=r"(r[1]), "=r"(r[2]), "=r"(r[3]) : "r"(addr));
}
__device__ __forceinline__ void ldmatrix_x2(uint32_t* r, uint32_t addr) {
    asm volatile("ldmatrix.sync.aligned.m8n8.x2.shared.b16 {%0,%1}, [%2];"
        : "=r"(r[0]), "=r"(r[1]) : "r"(addr));
}
__device__ __forceinline__ void mma_bf16(float* d, const uint32_t* a, const uint32_t* b) {
    asm volatile(
        "mma.sync.aligned.m16n8k16.row.col.f32.bf16.bf16.f32 "
        "{%0,%1,%2,%3}, {%4,%5,%6,%7}, {%8,%9}, {%0,%1,%2,%3};"
        : "+f"(d[0]), "+f"(d[1]), "+f"(d[2]), "+f"(d[3])
        : "r"(a[0]), "r"(a[1]), "r"(a[2]), "r"(a[3]), "r"(b[0]), "r"(b[1]));
}
__device__ __forceinline__ void mma_f16(float* d, const uint32_t* a, const uint32_t* b) {
    asm volatile(
        "mma.sync.aligned.m16n8k16.row.col.f32.f16.f16.f32 "
        "{%0,%1,%2,%3}, {%4,%5,%6,%7}, {%8,%9}, {%0,%1,%2,%3};"
        : "+f"(d[0]), "+f"(d[1]), "+f"(d[2]), "+f"(d[3])
        : "r"(a[0]), "r"(a[1]), "r"(a[2]), "r"(a[3]), "r"(b[0]), "r"(b[1]));
}
template <typename ET>
__device__ __forceinline__ void mma_et(float* d, const uint32_t* a, const uint32_t* b);
template <>
__device__ __forceinline__ void mma_et<__nv_bfloat16>(float* d, const uint32_t* a, const uint32_t* b) {
    mma_bf16(d, a, b);
}
template <>
__device__ __forceinline__ void mma_et<__half>(float* d, const uint32_t* a, const uint32_t* b) {
    mma_f16(d, a, b);
}
#define CP_ASYNC16(dst, src) \
    asm volatile("cp.async.cg.shared.global [%0], [%1], 16;" \
        :: "r"(dst), "l"(src) : "memory")
#define CP_COMMIT() asm volatile("cp.async.commit_group;" ::: "memory")
#define CP_WAIT(n)  asm volatile("cp.async.wait_group %0;" :: "n"(n) : "memory")

__device__ __forceinline__ uint32_t pack_h2(float lo, float hi) {
    __half2 h = __floats2half2_rn(lo, hi);
    return *reinterpret_cast<uint32_t*>(&h);
}

// ---------------------------------------------------------------------------
// Conversion kernels
// ---------------------------------------------------------------------------
// fp32 -> fp16, straight layout copy
__global__ void __launch_bounds__(256)
conv_act(const float4* __restrict__ x, __half2* __restrict__ out, int n4)
{
    int i = blockIdx.x * blockDim.x + threadIdx.x;
    if (i >= n4) return;
    float4 v = x[i];
    out[2 * i]     = __floats2half2_rn(v.x, v.y);
    out[2 * i + 1] = __floats2half2_rn(v.z, v.w);
}

// W[K,N] fp32 -> W^T[N,K] fp16
__global__ void __launch_bounds__(256)
conv_wT(const float* __restrict__ w, __half* __restrict__ out)
{
    __shared__ float t[32][33];
    const int k0 = blockIdx.y * 32, n0 = blockIdx.x * 32;
    const int tx = threadIdx.x, ty = threadIdx.y;   // (32, 8)
#pragma unroll
    for (int i = 0; i < 32; i += 8)
        t[ty + i][tx] = w[(size_t)(k0 + ty + i) * DM + n0 + tx];
    __syncthreads();
#pragma unroll
    for (int i = 0; i < 32; i += 8)
        out[(size_t)(n0 + ty + i) * DM + k0 + tx] = __float2half(t[tx][ty + i]);
}

// fp32 -> bf16 hi|lo (3-term split, O projection only)
__global__ void __launch_bounds__(256)
split_act(const float4* __restrict__ x, __nv_bfloat162* __restrict__ A2, int n4)
{
    int i = blockIdx.x * blockDim.x + threadIdx.x;
    if (i >= n4) return;
    float4 v = x[i];
    int m  = i >> 8;
    int kq = i & 255;
    __nv_bfloat162* hi = A2 + (size_t)m * (K2 / 2) + kq * 2;
    __nv_bfloat162* lo = hi + DM / 2;
    __nv_bfloat16 hx = __float2bfloat16(v.x);
    __nv_bfloat16 hy = __float2bfloat16(v.y);
    __nv_bfloat16 hz = __float2bfloat16(v.z);
    __nv_bfloat16 hw = __float2bfloat16(v.w);
    hi[0] = __halves2bfloat162(hx, hy);
    hi[1] = __halves2bfloat162(hz, hw);
    lo[0] = __halves2bfloat162(__float2bfloat16(v.x - __bfloat162float(hx)),
                               __float2bfloat16(v.y - __bfloat162float(hy)));
    lo[1] = __halves2bfloat162(__float2bfloat16(v.z - __bfloat162float(hz)),
                               __float2bfloat16(v.w - __bfloat162float(hw)));
}

__global__ void __launch_bounds__(256)
split_wT(const float* __restrict__ w, __nv_bfloat16* __restrict__ W2)
{
    __shared__ float t[32][33];
    const int k0 = blockIdx.y * 32, n0 = blockIdx.x * 32;
    const int tx = threadIdx.x, ty = threadIdx.y;   // (32, 8)
#pragma unroll
    for (int i = 0; i < 32; i += 8)
        t[ty + i][tx] = w[(size_t)(k0 + ty + i) * DM + n0 + tx];
    __syncthreads();
#pragma unroll
    for (int i = 0; i < 32; i += 8) {
        float v = t[tx][ty + i];
        __nv_bfloat16 h = __float2bfloat16(v);
        size_t o = (size_t)(n0 + ty + i) * K2 + k0 + tx;
        W2[o]      = h;
        W2[o + DM] = __float2bfloat16(v - __bfloat162float(h));
    }
}

// ---------------------------------------------------------------------------
// HMMA GEMM, templated:
//   SPLIT3=1: ET=bf16, K-stride 2048, 96 k-tiles (3-term hi/lo split)
//   SPLIT3=0: ET=fp16, K-stride 1024, 32 k-tiles (plain)
// 128x128x32 tiles, 256 thr (2x4 warps, 64x32 warp tile), cp.async 2-stage.
// ---------------------------------------------------------------------------
#define BM 128
#define BN 128
#define BK 32
#define LDT 40
#define TILE_B (BM * LDT * 2)

__device__ __forceinline__ int a_koff3(int kt) {
    return ((kt >= 64) ? DM : 0) + (kt & 31) * BK;
}
__device__ __forceinline__ int w_koff3(int kt) {
    return ((kt >= 32 && kt < 64) ? DM : 0) + (kt & 31) * BK;
}
__device__ __forceinline__ void store2(float* p, float x, float y) {
    *reinterpret_cast<float2*>(p) = make_float2(x, y);
}
__device__ __forceinline__ void store2(__half* p, float x, float y) {
    *reinterpret_cast<__half2*>(p) = __floats2half2_rn(x, y);
}

template <typename ET, typename OT, int SCATTER, int SPLIT3>
__global__ void __launch_bounds__(256)
gemm_hmma(const ET* __restrict__ A, const ET* __restrict__ W,
          const float* __restrict__ bias, OT* __restrict__ out, float scale)
{
    constexpr int NKT     = SPLIT3 ? 96 : 32;
    constexpr int KSTRIDE = SPLIT3 ? K2 : DM;

    __shared__ __align__(16) ET As[2][BM][LDT];
    __shared__ __align__(16) ET Bs[2][BN][LDT];

    const int tid  = threadIdx.x;
    const int wid  = tid >> 5;
    const int lane = tid & 31;
    const int warp_m = wid >> 2;
    const int warp_n = wid & 3;
    const int m0 = blockIdx.y * BM;
    const int n0 = blockIdx.x * BN;

    const uint32_t sA = smem_to_u32(As);
    const uint32_t sB = smem_to_u32(Bs);

    float acc[4][4][4];
#pragma unroll
    for (int i = 0; i < 4; i++)
#pragma unroll
        for (int j = 0; j < 4; j++)
#pragma unroll
            for (int c = 0; c < 4; c++) acc[i][j][c] = 0.f;

    {
        const int ka = SPLIT3 ? a_koff3(0) : 0;
        const int kw = SPLIT3 ? w_koff3(0) : 0;
#pragma unroll
        for (int i = 0; i < 2; i++) {
            int c = tid + i * 256;
            int r = c >> 2, q = c & 3;
            CP_ASYNC16(sA + r * 80 + q * 16, A + (size_t)(m0 + r) * KSTRIDE + ka + q * 8);
            CP_ASYNC16(sB + r * 80 + q * 16, W + (size_t)(n0 + r) * KSTRIDE + kw + q * 8);
        }
        CP_COMMIT();
    }

    for (int kt = 0; kt < NKT; ++kt) {
        const int buf = kt & 1;
        if (kt + 1 < NKT) {
            const int nb = (kt + 1) & 1;
            const int ka = SPLIT3 ? a_koff3(kt + 1) : (kt + 1) * BK;
            const int kw = SPLIT3 ? w_koff3(kt + 1) : (kt + 1) * BK;
#pragma unroll
            for (int i = 0; i < 2; i++) {
                int c = tid + i * 256;
                int r = c >> 2, q = c & 3;
                CP_ASYNC16(sA + nb * TILE_B + r * 80 + q * 16,
                           A + (size_t)(m0 + r) * KSTRIDE + ka + q * 8);
                CP_ASYNC16(sB + nb * TILE_B + r * 80 + q * 16,
                           W + (size_t)(n0 + r) * KSTRIDE + kw + q * 8);
            }
            CP_COMMIT();
            CP_WAIT(1);
        } else {
            CP_WAIT(0);
        }
        __syncthreads();

        const uint32_t sAb = sA + buf * TILE_B;
        const uint32_t sBb = sB + buf * TILE_B;
#pragma unroll
        for (int kf = 0; kf < 2; ++kf) {
            uint32_t af[4][4], bf[4][2];
#pragma unroll
            for (int mf = 0; mf < 4; ++mf) {
                uint32_t addr = sAb +
                    ((warp_m * 64 + mf * 16 + (lane & 15)) * LDT
                     + kf * 16 + (lane >> 4) * 8) * 2;
                ldmatrix_x4(af[mf], addr);
            }
#pragma unroll
            for (int nf = 0; nf < 4; ++nf) {
                uint32_t addr = sBb +
                    ((warp_n * 32 + nf * 8 + (lane & 7)) * LDT
                     + kf * 16 + ((lane >> 3) & 1) * 8) * 2;
                ldmatrix_x2(bf[nf], addr);
            }
#pragma unroll
            for (int mf = 0; mf < 4; ++mf)
#pragma unroll
                for (int nf = 0; nf < 4; ++nf)
                    mma_et<ET>(acc[mf][nf], af[mf], bf[nf]);
        }
        __syncthreads();
    }

    const int grp = lane >> 2;
    const int qd  = lane & 3;
#pragma unroll
    for (int mf = 0; mf < 4; ++mf) {
#pragma unroll
        for (int nf = 0; nf < 4; ++nf) {
            int m = m0 + warp_m * 64 + mf * 16 + grp;
            int n = n0 + warp_n * 32 + nf * 8 + qd * 2;
            float b0 = bias[n], b1 = bias[n + 1];
            float x0 = (acc[mf][nf][0] + b0) * scale;
            float y0 = (acc[mf][nf][1] + b1) * scale;
            float x1 = (acc[mf][nf][2] + b0) * scale;
            float y1 = (acc[mf][nf][3] + b1) * scale;
            if (SCATTER) {
                int bb = m >> 11, t = m & 2047;
                int hh = n >> 6,  dd = n & 63;
                size_t base = (((size_t)bb * NH + hh) * TSEQ) * HD + dd;
                store2(out + base + (size_t)t * HD, x0, y0);
                store2(out + base + (size_t)(t + 8) * HD, x1, y1);
            } else {
                store2(out + (size_t)m * DM + n, x0, y0);
                store2(out + (size_t)(m + 8) * DM + n, x1, y1);
            }
        }
    }
}

// ---------------------------------------------------------------------------
// HMMA causal flash attention, fp16 operands / fp32 softmax+accum (R8, proven)
// ---------------------------------------------------------------------------
__global__ void __launch_bounds__(128)
attn_hmma(const __half* __restrict__ Q, const __half* __restrict__ K,
          const __half* __restrict__ V, float* __restrict__ ctx)
{
    __shared__ __align__(16) __half Qs[64][72];
    __shared__ __align__(16) __half Ks[64][72];
    __shared__ __align__(16) __half Vt[64][72];   // [dim][key] (transposed at fill)

    const int qt   = gridDim.x - 1 - blockIdx.x;
    const int bh   = blockIdx.y;
    const int tid  = threadIdx.x;
    const int wid  = tid >> 5;
    const int lane = tid & 31;
    const int q0   = qt * 64;

    const __half* Qb = Q + (size_t)bh * TSEQ * HD;
    const __half* Kb = K + (size_t)bh * TSEQ * HD;
    const __half* Vb = V + (size_t)bh * TSEQ * HD;

    const uint32_t sQ = smem_to_u32(Qs);
    const uint32_t sK = smem_to_u32(Ks);
    const uint32_t sV = smem_to_u32(Vt);

#pragma unroll
    for (int it = 0; it < 4; ++it) {
        int lin = tid + it * 128;
        int r = lin >> 3, qd = lin & 7;
        *reinterpret_cast<float4*>(&Qs[r][qd * 8]) =
            *reinterpret_cast<const float4*>(&Qb[(size_t)(q0 + r) * HD + qd * 8]);
    }
    __syncthreads();

    uint32_t aq[4][4];
#pragma unroll
    for (int kc = 0; kc < 4; ++kc) {
        uint32_t addr = sQ + ((wid * 16 + (lane & 15)) * 72 + kc * 16 + 8 * (lane >> 4)) * 2;
        ldmatrix_x4(aq[kc], addr);
    }

    float o[8][4];
#pragma unroll
    for (int i = 0; i < 8; i++)
#pragma unroll
        for (int c = 0; c < 4; c++) o[i][c] = 0.f;
    float m_a = -1e30f, m_b = -1e30f, l_a = 0.f, l_b = 0.f;

    for (int kt = 0; kt <= qt; ++kt) {
        const int k0 = kt * 64;
        __syncthreads();
#pragma unroll
        for (int it = 0; it < 4; ++it) {
            int lin = tid + it * 128;
            int r = lin >> 3, qd = lin & 7;
            *reinterpret_cast<float4*>(&Ks[r][qd * 8]) =
                *reinterpret_cast<const float4*>(&Kb[(size_t)(k0 + r) * HD + qd * 8]);
        }
#pragma unroll
        for (int it = 0; it < 4; ++it) {
            int lin = tid + it * 128;
            int key = lin >> 3, qd = lin & 7;
            float4 v = *reinterpret_cast<const float4*>(&Vb[(size_t)(k0 + key) * HD + qd * 8]);
            const __half* hv = reinterpret_cast<const __half*>(&v);
#pragma unroll
            for (int i = 0; i < 8; ++i) {
                int ii = (i + qd) & 7;
                Vt[qd * 8 + ii][key] = hv[ii];
            }
        }
        __syncthreads();

        float s[8][4];
#pragma unroll
        for (int i = 0; i < 8; i++)
#pragma unroll
            for (int c = 0; c < 4; c++) s[i][c] = 0.f;
#pragma unroll
        for (int kc = 0; kc < 4; ++kc) {
#pragma unroll
            for (int j = 0; j < 4; ++j) {
                uint32_t bk[4];
                uint32_t addr = sK +
                    ((j * 16 + ((lane >> 4) << 3) + (lane & 7)) * 72
                     + kc * 16 + 8 * ((lane >> 3) & 1)) * 2;
                ldmatrix_x4(bk, addr);
                mma_f16(s[2 * j],     aq[kc], bk);
                mma_f16(s[2 * j + 1], aq[kc], bk + 2);
            }
        }

        if (kt == qt) {
            const int ra = wid * 16 + (lane >> 2);
#pragma unroll
            for (int nf = 0; nf < 8; ++nf) {
#pragma unroll
                for (int c = 0; c < 4; ++c) {
                    int key = nf * 8 + 2 * (lane & 3) + (c & 1);
                    int row = ra + 8 * (c >> 1);
                    if (key > row) s[nf][c] = -1e30f;
                }
            }
        }

        float mxa = -1e30f, mxb = -1e30f;
#pragma unroll
        for (int nf = 0; nf < 8; ++nf) {
            mxa = fmaxf(mxa, fmaxf(s[nf][0], s[nf][1]));
            mxb = fmaxf(mxb, fmaxf(s[nf][2], s[nf][3]));
        }
        mxa = fmaxf(mxa, __shfl_xor_sync(0xffffffffu, mxa, 1));
        mxa = fmaxf(mxa, __shfl_xor_sync(0xffffffffu, mxa, 2));
        mxb = fmaxf(mxb, __shfl_xor_sync(0xffffffffu, mxb, 1));
        mxb = fmaxf(mxb, __shfl_xor_sync(0xffffffffu, mxb, 2));
        float mna = fmaxf(m_a, mxa), mnb = fmaxf(m_b, mxb);
        float ala = __expf(m_a - mna), alb = __expf(m_b - mnb);
        float sa = 0.f, sb = 0.f;
#pragma unroll
        for (int nf = 0; nf < 8; ++nf) {
            s[nf][0] = __expf(s[nf][0] - mna);
            s[nf][1] = __expf(s[nf][1] - mna);
            s[nf][2] = __expf(s[nf][2] - mnb);
            s[nf][3] = __expf(s[nf][3] - mnb);
            sa += s[nf][0] + s[nf][1];
            sb += s[nf][2] + s[nf][3];
        }
        sa += __shfl_xor_sync(0xffffffffu, sa, 1);
        sa += __shfl_xor_sync(0xffffffffu, sa, 2);
        sb += __shfl_xor_sync(0xffffffffu, sb, 1);
        sb += __shfl_xor_sync(0xffffffffu, sb, 2);
        l_a = l_a * ala + sa;  m_a = mna;
        l_b = l_b * alb + sb;  m_b = mnb;
#pragma unroll
        for (int nf = 0; nf < 8; ++nf) {
            o[nf][0] *= ala; o[nf][1] *= ala;
            o[nf][2] *= alb; o[nf][3] *= alb;
        }

#pragma unroll
        for (int kc2 = 0; kc2 < 4; ++kc2) {
            uint32_t ap[4];
            ap[0] = pack_h2(s[2 * kc2][0],     s[2 * kc2][1]);
            ap[1] = pack_h2(s[2 * kc2][2],     s[2 * kc2][3]);
            ap[2] = pack_h2(s[2 * kc2 + 1][0], s[2 * kc2 + 1][1]);
            ap[3] = pack_h2(s[2 * kc2 + 1][2], s[2 * kc2 + 1][3]);
#pragma unroll
            for (int nf2 = 0; nf2 < 4; ++nf2) {
                uint32_t bv[4];
                uint32_t addr = sV +
                    ((nf2 * 16 + ((lane >> 4) << 3) + (lane & 7)) * 72
                     + kc2 * 16 + 8 * ((lane >> 3) & 1)) * 2;
                ldmatrix_x4(bv, addr);
                mma_f16(o[2 * nf2],     ap, bv);
                mma_f16(o[2 * nf2 + 1], ap, bv + 2);
            }
        }
    }

    const int b = bh >> 4;
    const int h = bh & 15;
    const int ta = q0 + wid * 16 + (lane >> 2);
    const int tb = ta + 8;
    const float inva = 1.0f / l_a;
    const float invb = 1.0f / l_b;
#pragma unroll
    for (int nf = 0; nf < 8; ++nf) {
        int col = h * HD + nf * 8 + 2 * (lane & 3);
        *reinterpret_cast<float2*>(&ctx[(size_t)(b * TSEQ + ta) * DM + col]) =
            make_float2(o[nf][0] * inva, o[nf][1] * inva);
        *reinterpret_cast<float2*>(&ctx[(size_t)(b * TSEQ + tb) * DM + col]) =
            make_float2(o[nf][2] * invb, o[nf][3] * invb);
    }
}

// ---------------------------------------------------------------------------
extern "C" void kernel_launch(void* const* d_in, const int* in_sizes, int n_in,
                              void* d_out, int out_size)
{
    const float* q  = (const float*)d_in[0];
    const float* k  = (const float*)d_in[1];
    const float* v  = (const float*)d_in[2];
    const float* wq = (const float*)d_in[3];
    const float* bq = (const float*)d_in[4];
    const float* wk = (const float*)d_in[5];
    const float* bk = (const float*)d_in[6];
    const float* wv = (const float*)d_in[7];
    const float* bv = (const float*)d_in[8];
    const float* wo = (const float*)d_in[9];
    const float* bo = (const float*)d_in[10];

    __half *Qp, *Kp, *Vp, *Afp, *Wfp;
    float *Cp;
    __nv_bfloat16 *A2p, *W2p;
    cudaGetSymbolAddress((void**)&Qp,  g_Qh);
    cudaGetSymbolAddress((void**)&Kp,  g_Kh);
    cudaGetSymbolAddress((void**)&Vp,  g_Vh);
    cudaGetSymbolAddress((void**)&Cp,  g_ctx);
    cudaGetSymbolAddress((void**)&Afp, g_Af);
    cudaGetSymbolAddress((void**)&Wfp, g_Wf);
    cudaGetSymbolAddress((void**)&A2p, g_A2);
    cudaGetSymbolAddress((void**)&W2p, g_W2);

    const int n4 = MROWS * DM / 4;
    dim3 sblk(256), sgrid((n4 + 255) / 256);
    dim3 wgrid(DM / 32, DM / 32), wblk(32, 8);
    dim3 gblk(256), ggrid(DM / BN, MROWS / BM);   // (8, 64)

    // Q projection: plain fp16 (pre-scaled by 1/sqrt(hd) = 0.125)
    conv_wT<<<wgrid, wblk>>>(wq, Wfp);
    conv_act<<<sgrid, sblk>>>((const float4*)q, (__half2*)Afp, n4);
    gemm_hmma<__half, __half, 1, 0><<<ggrid, gblk>>>(Afp, Wfp, bq, Qp, 0.125f);
    // K projection: plain fp16
    conv_wT<<<wgrid, wblk>>>(wk, Wfp);
    conv_act<<<sgrid, sblk>>>((const float4*)k, (__half2*)Afp, n4);
    gemm_hmma<__half, __half, 1, 0><<<ggrid, gblk>>>(Afp, Wfp, bk, Kp, 1.0f);
    // V projection: plain fp16
    conv_wT<<<wgrid, wblk>>>(wv, Wfp);
    conv_act<<<sgrid, sblk>>>((const float4*)v, (__half2*)Afp, n4);
    gemm_hmma<__half, __half, 1, 0><<<ggrid, gblk>>>(Afp, Wfp, bv, Vp, 1.0f);

    // attention (HMMA fp16)
    attn_hmma<<<dim3(TSEQ / 64, BSZ * NH), dim3(128)>>>(Qp, Kp, Vp, Cp);

    // output projection: 3-term bf16 split (precision anchor), fp32 out
    split_wT<<<wgrid, wblk>>>(wo, W2p);
    split_act<<<sgrid, sblk>>>((const float4*)Cp, (__nv_bfloat162*)A2p, n4);
    gemm_hmma<__nv_bfloat16, float, 0, 1><<<ggrid, gblk>>>(A2p, W2p, bo, (float*)d_out, 1.0f);
}

// round 10
// speedup vs baseline: 5.7589x; 1.4004x over previous
#include <cuda_runtime.h>
#include <cuda_fp16.h>
#include <cstdint>

#define DM   1024
#define NH   16
#define HD   64
#define BSZ  4
#define TSEQ 2048
#define MROWS (BSZ * TSEQ)   // 8192

// ---------------------------------------------------------------------------
// Scratch (allocation-free rule: __device__ globals)
// ---------------------------------------------------------------------------
__device__ __align__(16) __half g_Qh[(size_t)BSZ * NH * TSEQ * HD];  // [B,H,T,hd], pre-scaled 1/8
__device__ __align__(16) __half g_Kh[(size_t)BSZ * NH * TSEQ * HD];
__device__ __align__(16) __half g_Vh[(size_t)BSZ * NH * TSEQ * HD];
__device__ __align__(16) __half g_ctxh[(size_t)MROWS * DM];          // [B,T,D] fp16
__device__ __align__(16) __half g_Af[(size_t)MROWS * DM];            // fp16 activations
__device__ __align__(16) __half g_Wf[(size_t)DM * DM];               // fp16 W^T [N,K]

// ---------------------------------------------------------------------------
// PTX helpers (legal on plain sm_100)
// ---------------------------------------------------------------------------
__device__ __forceinline__ uint32_t smem_to_u32(const void* p) {
    uint32_t a;
    asm("{ .reg .u64 t; cvta.to.shared.u64 t, %1; cvt.u32.u64 %0, t; }"
        : "=r"(a) : "l"(p));
    return a;
}
__device__ __forceinline__ void ldmatrix_x4(uint32_t* r, uint32_t addr) {
    asm volatile("ldmatrix.sync.aligned.m8n8.x4.shared.b16 {%0,%1,%2,%3}, [%4];"
        : "=r"(r[0]), "=r"(r[1]), "=r"(r[2]), "=r"(r[3]) : "r"(addr));
}
__device__ __forceinline__ void ldmatrix_x2(uint32_t* r, uint32_t addr) {
    asm volatile("ldmatrix.sync.aligned.m8n8.x2.shared.b16 {%0,%1}, [%2];"
        : "=r"(r[0]), "=r"(r[1]) : "r"(addr));
}
__device__ __forceinline__ void mma_f16(float* d, const uint32_t* a, const uint32_t* b) {
    asm volatile(
        "mma.sync.aligned.m16n8k16.row.col.f32.f16.f16.f32 "
        "{%0,%1,%2,%3}, {%4,%5,%6,%7}, {%8,%9}, {%0,%1,%2,%3};"
        : "+f"(d[0]), "+f"(d[1]), "+f"(d[2]), "+f"(d[3])
        : "r"(a[0]), "r"(a[1]), "r"(a[2]), "r"(a[3]), "r"(b[0]), "r"(b[1]));
}
#define CP_ASYNC16(dst, src) \
    asm volatile("cp.async.cg.shared.global [%0], [%1], 16;" \
        :: "r"(dst), "l"(src) : "memory")
#define CP_COMMIT() asm volatile("cp.async.commit_group;" ::: "memory")
#define CP_WAIT(n)  asm volatile("cp.async.wait_group %0;" :: "n"(n) : "memory")

__device__ __forceinline__ uint32_t pack_h2(float lo, float hi) {
    __half2 h = __floats2half2_rn(lo, hi);
    return *reinterpret_cast<uint32_t*>(&h);
}

// ---------------------------------------------------------------------------
// Conversion kernels: fp32 -> fp16
// ---------------------------------------------------------------------------
__global__ void __launch_bounds__(256)
conv_act(const float4* __restrict__ x, __half2* __restrict__ out, int n4)
{
    int i = blockIdx.x * blockDim.x + threadIdx.x;
    if (i >= n4) return;
    float4 v = x[i];
    out[2 * i]     = __floats2half2_rn(v.x, v.y);
    out[2 * i + 1] = __floats2half2_rn(v.z, v.w);
}

// W[K,N] fp32 -> W^T[N,K] fp16
__global__ void __launch_bounds__(256)
conv_wT(const float* __restrict__ w, __half* __restrict__ out)
{
    __shared__ float t[32][33];
    const int k0 = blockIdx.y * 32, n0 = blockIdx.x * 32;
    const int tx = threadIdx.x, ty = threadIdx.y;   // (32, 8)
#pragma unroll
    for (int i = 0; i < 32; i += 8)
        t[ty + i][tx] = w[(size_t)(k0 + ty + i) * DM + n0 + tx];
    __syncthreads();
#pragma unroll
    for (int i = 0; i < 32; i += 8)
        out[(size_t)(n0 + ty + i) * DM + k0 + tx] = __float2half(t[tx][ty + i]);
}

// ---------------------------------------------------------------------------
// HMMA GEMM fp16: C[M=8192, N=1024] = A[M,1024] @ W[N,1024]^T + bias
// 128x128x64 tiles, 16 k-tiles, 256 thr (2x4 warps, 64x32 warp tile),
// cp.async 2-stage, dynamic smem (73.7 KB).
// ---------------------------------------------------------------------------
#define BM 128
#define BN 128
#define BK 64
#define LDT 72                           // padded smem row (halfs): 144B, 9 quads (odd)
#define TILE_B (BM * LDT * 2)            // 18432 bytes per operand tile
#define GSMEM  (4 * TILE_B)              // 73728
#define NKT (DM / BK)                    // 16

__device__ __forceinline__ void store2(float* p, float x, float y) {
    *reinterpret_cast<float2*>(p) = make_float2(x, y);
}
__device__ __forceinline__ void store2(__half* p, float x, float y) {
    *reinterpret_cast<__half2*>(p) = __floats2half2_rn(x, y);
}

template <typename OT, int SCATTER>
__global__ void __launch_bounds__(256)
gemm_hmma(const __half* __restrict__ A, const __half* __restrict__ W,
          const float* __restrict__ bias, OT* __restrict__ out, float scale)
{
    extern __shared__ char smem[];
    // layout: [buf0 A][buf0 B][buf1 A][buf1 B]
    const uint32_t sbase = smem_to_u32(smem);

    const int tid  = threadIdx.x;
    const int wid  = tid >> 5;
    const int lane = tid & 31;
    const int warp_m = wid >> 2;
    const int warp_n = wid & 3;
    const int m0 = blockIdx.y * BM;
    const int n0 = blockIdx.x * BN;

    float acc[4][4][4];
#pragma unroll
    for (int i = 0; i < 4; i++)
#pragma unroll
        for (int j = 0; j < 4; j++)
#pragma unroll
            for (int c = 0; c < 4; c++) acc[i][j][c] = 0.f;

    // prefetch k-tile 0 into buf 0
#pragma unroll
    for (int i = 0; i < 4; i++) {
        int lin = tid + i * 256;           // 0..1023
        int r = lin >> 3, q = lin & 7;     // row, 16B-quad (8 quads = 128B = 64 halfs)
        CP_ASYNC16(sbase + r * 144 + q * 16,
                   A + (size_t)(m0 + r) * DM + q * 8);
        CP_ASYNC16(sbase + TILE_B + r * 144 + q * 16,
                   W + (size_t)(n0 + r) * DM + q * 8);
    }
    CP_COMMIT();

    for (int kt = 0; kt < NKT; ++kt) {
        const int buf = kt & 1;
        if (kt + 1 < NKT) {
            const uint32_t nboff = ((kt + 1) & 1) * (2 * TILE_B);
            const int k0 = (kt + 1) * BK;
#pragma unroll
            for (int i = 0; i < 4; i++) {
                int lin = tid + i * 256;
                int r = lin >> 3, q = lin & 7;
                CP_ASYNC16(sbase + nboff + r * 144 + q * 16,
                           A + (size_t)(m0 + r) * DM + k0 + q * 8);
                CP_ASYNC16(sbase + nboff + TILE_B + r * 144 + q * 16,
                           W + (size_t)(n0 + r) * DM + k0 + q * 8);
            }
            CP_COMMIT();
            CP_WAIT(1);
        } else {
            CP_WAIT(0);
        }
        __syncthreads();

        const uint32_t sAb = sbase + buf * (2 * TILE_B);
        const uint32_t sBb = sAb + TILE_B;
#pragma unroll
        for (int kf = 0; kf < 4; ++kf) {
            uint32_t af[4][4], bf[4][2];
#pragma unroll
            for (int mf = 0; mf < 4; ++mf) {
                uint32_t addr = sAb +
                    (warp_m * 64 + mf * 16 + (lane & 15)) * 144
                    + (kf * 16 + 8 * (lane >> 4)) * 2;
                ldmatrix_x4(af[mf], addr);
            }
#pragma unroll
            for (int nf = 0; nf < 4; ++nf) {
                uint32_t addr = sBb +
                    (warp_n * 32 + nf * 8 + (lane & 7)) * 144
                    + (kf * 16 + 8 * ((lane >> 3) & 1)) * 2;
                ldmatrix_x2(bf[nf], addr);
            }
#pragma unroll
            for (int mf = 0; mf < 4; ++mf)
#pragma unroll
                for (int nf = 0; nf < 4; ++nf)
                    mma_f16(acc[mf][nf], af[mf], bf[nf]);
        }
        __syncthreads();   // all warps done with buf before it is overwritten
    }

    const int grp = lane >> 2;
    const int qd  = lane & 3;
#pragma unroll
    for (int mf = 0; mf < 4; ++mf) {
#pragma unroll
        for (int nf = 0; nf < 4; ++nf) {
            int m = m0 + warp_m * 64 + mf * 16 + grp;
            int n = n0 + warp_n * 32 + nf * 8 + qd * 2;
            float b0 = bias[n], b1 = bias[n + 1];
            float x0 = (acc[mf][nf][0] + b0) * scale;
            float y0 = (acc[mf][nf][1] + b1) * scale;
            float x1 = (acc[mf][nf][2] + b0) * scale;
            float y1 = (acc[mf][nf][3] + b1) * scale;
            if (SCATTER) {
                int bb = m >> 11, t = m & 2047;
                int hh = n >> 6,  dd = n & 63;
                size_t base = (((size_t)bb * NH + hh) * TSEQ) * HD + dd;
                store2(out + base + (size_t)t * HD, x0, y0);
                store2(out + base + (size_t)(t + 8) * HD, x1, y1);
            } else {
                store2(out + (size_t)m * DM + n, x0, y0);
                store2(out + (size_t)(m + 8) * DM + n, x1, y1);
            }
        }
    }
}

// ---------------------------------------------------------------------------
// HMMA causal flash attention, fp16 operands / fp32 softmax+accum (R8, proven).
// Now writes fp16 ctx directly.
// ---------------------------------------------------------------------------
__global__ void __launch_bounds__(128)
attn_hmma(const __half* __restrict__ Q, const __half* __restrict__ K,
          const __half* __restrict__ V, __half* __restrict__ ctx)
{
    __shared__ __align__(16) __half Qs[64][72];
    __shared__ __align__(16) __half Ks[64][72];
    __shared__ __align__(16) __half Vt[64][72];   // [dim][key] (transposed at fill)

    const int qt   = gridDim.x - 1 - blockIdx.x;
    const int bh   = blockIdx.y;
    const int tid  = threadIdx.x;
    const int wid  = tid >> 5;
    const int lane = tid & 31;
    const int q0   = qt * 64;

    const __half* Qb = Q + (size_t)bh * TSEQ * HD;
    const __half* Kb = K + (size_t)bh * TSEQ * HD;
    const __half* Vb = V + (size_t)bh * TSEQ * HD;

    const uint32_t sQ = smem_to_u32(Qs);
    const uint32_t sK = smem_to_u32(Ks);
    const uint32_t sV = smem_to_u32(Vt);

#pragma unroll
    for (int it = 0; it < 4; ++it) {
        int lin = tid + it * 128;
        int r = lin >> 3, qd = lin & 7;
        *reinterpret_cast<float4*>(&Qs[r][qd * 8]) =
            *reinterpret_cast<const float4*>(&Qb[(size_t)(q0 + r) * HD + qd * 8]);
    }
    __syncthreads();

    uint32_t aq[4][4];
#pragma unroll
    for (int kc = 0; kc < 4; ++kc) {
        uint32_t addr = sQ + ((wid * 16 + (lane & 15)) * 72 + kc * 16 + 8 * (lane >> 4)) * 2;
        ldmatrix_x4(aq[kc], addr);
    }

    float o[8][4];
#pragma unroll
    for (int i = 0; i < 8; i++)
#pragma unroll
        for (int c = 0; c < 4; c++) o[i][c] = 0.f;
    float m_a = -1e30f, m_b = -1e30f, l_a = 0.f, l_b = 0.f;

    for (int kt = 0; kt <= qt; ++kt) {
        const int k0 = kt * 64;
        __syncthreads();
#pragma unroll
        for (int it = 0; it < 4; ++it) {
            int lin = tid + it * 128;
            int r = lin >> 3, qd = lin & 7;
            *reinterpret_cast<float4*>(&Ks[r][qd * 8]) =
                *reinterpret_cast<const float4*>(&Kb[(size_t)(k0 + r) * HD + qd * 8]);
        }
#pragma unroll
        for (int it = 0; it < 4; ++it) {
            int lin = tid + it * 128;
            int key = lin >> 3, qd = lin & 7;
            float4 v = *reinterpret_cast<const float4*>(&Vb[(size_t)(k0 + key) * HD + qd * 8]);
            const __half* hv = reinterpret_cast<const __half*>(&v);
#pragma unroll
            for (int i = 0; i < 8; ++i) {
                int ii = (i + qd) & 7;
                Vt[qd * 8 + ii][key] = hv[ii];
            }
        }
        __syncthreads();

        float s[8][4];
#pragma unroll
        for (int i = 0; i < 8; i++)
#pragma unroll
            for (int c = 0; c < 4; c++) s[i][c] = 0.f;
#pragma unroll
        for (int kc = 0; kc < 4; ++kc) {
#pragma unroll
            for (int j = 0; j < 4; ++j) {
                uint32_t bk[4];
                uint32_t addr = sK +
                    ((j * 16 + ((lane >> 4) << 3) + (lane & 7)) * 72
                     + kc * 16 + 8 * ((lane >> 3) & 1)) * 2;
                ldmatrix_x4(bk, addr);
                mma_f16(s[2 * j],     aq[kc], bk);
                mma_f16(s[2 * j + 1], aq[kc], bk + 2);
            }
        }

        if (kt == qt) {
            const int ra = wid * 16 + (lane >> 2);
#pragma unroll
            for (int nf = 0; nf < 8; ++nf) {
#pragma unroll
                for (int c = 0; c < 4; ++c) {
                    int key = nf * 8 + 2 * (lane & 3) + (c & 1);
                    int row = ra + 8 * (c >> 1);
                    if (key > row) s[nf][c] = -1e30f;
                }
            }
        }

        float mxa = -1e30f, mxb = -1e30f;
#pragma unroll
        for (int nf = 0; nf < 8; ++nf) {
            mxa = fmaxf(mxa, fmaxf(s[nf][0], s[nf][1]));
            mxb = fmaxf(mxb, fmaxf(s[nf][2], s[nf][3]));
        }
        mxa = fmaxf(mxa, __shfl_xor_sync(0xffffffffu, mxa, 1));
        mxa = fmaxf(mxa, __shfl_xor_sync(0xffffffffu, mxa, 2));
        mxb = fmaxf(mxb, __shfl_xor_sync(0xffffffffu, mxb, 1));
        mxb = fmaxf(mxb, __shfl_xor_sync(0xffffffffu, mxb, 2));
        float mna = fmaxf(m_a, mxa), mnb = fmaxf(m_b, mxb);
        float ala = __expf(m_a - mna), alb = __expf(m_b - mnb);
        float sa = 0.f, sb = 0.f;
#pragma unroll
        for (int nf = 0; nf < 8; ++nf) {
            s[nf][0] = __expf(s[nf][0] - mna);
            s[nf][1] = __expf(s[nf][1] - mna);
            s[nf][2] = __expf(s[nf][2] - mnb);
            s[nf][3] = __expf(s[nf][3] - mnb);
            sa += s[nf][0] + s[nf][1];
            sb += s[nf][2] + s[nf][3];
        }
        sa += __shfl_xor_sync(0xffffffffu, sa, 1);
        sa += __shfl_xor_sync(0xffffffffu, sa, 2);
        sb += __shfl_xor_sync(0xffffffffu, sb, 1);
        sb += __shfl_xor_sync(0xffffffffu, sb, 2);
        l_a = l_a * ala + sa;  m_a = mna;
        l_b = l_b * alb + sb;  m_b = mnb;
#pragma unroll
        for (int nf = 0; nf < 8; ++nf) {
            o[nf][0] *= ala; o[nf][1] *= ala;
            o[nf][2] *= alb; o[nf][3] *= alb;
        }

#pragma unroll
        for (int kc2 = 0; kc2 < 4; ++kc2) {
            uint32_t ap[4];
            ap[0] = pack_h2(s[2 * kc2][0],     s[2 * kc2][1]);
            ap[1] = pack_h2(s[2 * kc2][2],     s[2 * kc2][3]);
            ap[2] = pack_h2(s[2 * kc2 + 1][0], s[2 * kc2 + 1][1]);
            ap[3] = pack_h2(s[2 * kc2 + 1][2], s[2 * kc2 + 1][3]);
#pragma unroll
            for (int nf2 = 0; nf2 < 4; ++nf2) {
                uint32_t bv[4];
                uint32_t addr = sV +
                    ((nf2 * 16 + ((lane >> 4) << 3) + (lane & 7)) * 72
                     + kc2 * 16 + 8 * ((lane >> 3) & 1)) * 2;
                ldmatrix_x4(bv, addr);
                mma_f16(o[2 * nf2],     ap, bv);
                mma_f16(o[2 * nf2 + 1], ap, bv + 2);
            }
        }
    }

    const int b = bh >> 4;
    const int h = bh & 15;
    const int ta = q0 + wid * 16 + (lane >> 2);
    const int tb = ta + 8;
    const float inva = 1.0f / l_a;
    const float invb = 1.0f / l_b;
#pragma unroll
    for (int nf = 0; nf < 8; ++nf) {
        int col = h * HD + nf * 8 + 2 * (lane & 3);
        *reinterpret_cast<__half2*>(&ctx[(size_t)(b * TSEQ + ta) * DM + col]) =
            __floats2half2_rn(o[nf][0] * inva, o[nf][1] * inva);
        *reinterpret_cast<__half2*>(&ctx[(size_t)(b * TSEQ + tb) * DM + col]) =
            __floats2half2_rn(o[nf][2] * invb, o[nf][3] * invb);
    }
}

// ---------------------------------------------------------------------------
extern "C" void kernel_launch(void* const* d_in, const int* in_sizes, int n_in,
                              void* d_out, int out_size)
{
    const float* q  = (const float*)d_in[0];
    const float* k  = (const float*)d_in[1];
    const float* v  = (const float*)d_in[2];
    const float* wq = (const float*)d_in[3];
    const float* bq = (const float*)d_in[4];
    const float* wk = (const float*)d_in[5];
    const float* bk = (const float*)d_in[6];
    const float* wv = (const float*)d_in[7];
    const float* bv = (const float*)d_in[8];
    const float* wo = (const float*)d_in[9];
    const float* bo = (const float*)d_in[10];

    __half *Qp, *Kp, *Vp, *Cp, *Afp, *Wfp;
    cudaGetSymbolAddress((void**)&Qp,  g_Qh);
    cudaGetSymbolAddress((void**)&Kp,  g_Kh);
    cudaGetSymbolAddress((void**)&Vp,  g_Vh);
    cudaGetSymbolAddress((void**)&Cp,  g_ctxh);
    cudaGetSymbolAddress((void**)&Afp, g_Af);
    cudaGetSymbolAddress((void**)&Wfp, g_Wf);

    cudaFuncSetAttribute(gemm_hmma<__half, 1>,
                         cudaFuncAttributeMaxDynamicSharedMemorySize, GSMEM);
    cudaFuncSetAttribute(gemm_hmma<float, 0>,
                         cudaFuncAttributeMaxDynamicSharedMemorySize, GSMEM);

    const int n4 = MROWS * DM / 4;
    dim3 sblk(256), sgrid((n4 + 255) / 256);
    dim3 wgrid(DM / 32, DM / 32), wblk(32, 8);
    dim3 gblk(256), ggrid(DM / BN, MROWS / BM);   // (8, 64)

    // Q projection (pre-scaled by 1/sqrt(hd) = 0.125)
    conv_wT<<<wgrid, wblk>>>(wq, Wfp);
    conv_act<<<sgrid, sblk>>>((const float4*)q, (__half2*)Afp, n4);
    gemm_hmma<__half, 1><<<ggrid, gblk, GSMEM>>>(Afp, Wfp, bq, Qp, 0.125f);
    // K projection
    conv_wT<<<wgrid, wblk>>>(wk, Wfp);
    conv_act<<<sgrid, sblk>>>((const float4*)k, (__half2*)Afp, n4);
    gemm_hmma<__half, 1><<<ggrid, gblk, GSMEM>>>(Afp, Wfp, bk, Kp, 1.0f);
    // V projection
    conv_wT<<<wgrid, wblk>>>(wv, Wfp);
    conv_act<<<sgrid, sblk>>>((const float4*)v, (__half2*)Afp, n4);
    gemm_hmma<__half, 1><<<ggrid, gblk, GSMEM>>>(Afp, Wfp, bv, Vp, 1.0f);

    // attention (HMMA fp16, writes fp16 ctx)
    attn_hmma<<<dim3(TSEQ / 64, BSZ * NH), dim3(128)>>>(Qp, Kp, Vp, Cp);

    // output projection: plain fp16, fp32 out
    conv_wT<<<wgrid, wblk>>>(wo, Wfp);
    gemm_hmma<float, 0><<<ggrid, gblk, GSMEM>>>(Cp, Wfp, bo, (float*)d_out, 1.0f);
}